// round 5
// baseline (speedup 1.0000x reference)
#include <cuda_runtime.h>
#include <cstdint>

#define B_DIM 64
#define L_DIM 8192
#define C_DIM 128
#define NCH   64
#define MAX_TILES 4160   // >= sum ceil(cnt/2) <= (8192+2*64)/2

static __device__ int g_sorted[L_DIM];
static __device__ int g_tile_l0[MAX_TILES];
static __device__ int g_tile_l1[MAX_TILES];
static __device__ int g_tile_ch[MAX_TILES];
static __device__ int g_is64;

// ---------------- helpers ----------------
__device__ __forceinline__ uint32_t rtf32_u(float v) {   // fp32 -> tf32 (round-to-nearest), bits in b32
    uint32_t r; asm("cvt.rna.tf32.f32 %0, %1;" : "=r"(r) : "f"(v)); return r;
}
__device__ __forceinline__ float rtf32_f(float v) {
    return __uint_as_float(rtf32_u(v));
}
__device__ __forceinline__ float tanh_fast(float v) {
    float r; asm("tanh.approx.f32 %0, %1;" : "=f"(r) : "f"(v)); return r;
}

__device__ __forceinline__ void mma_tf32(float* d, const uint32_t* a, const uint32_t* b) {
    asm volatile(
        "mma.sync.aligned.m16n8k8.row.col.f32.tf32.tf32.f32 "
        "{%0,%1,%2,%3}, {%4,%5,%6,%7}, {%8,%9}, {%0,%1,%2,%3};"
        : "+f"(d[0]), "+f"(d[1]), "+f"(d[2]), "+f"(d[3])
        : "r"(a[0]), "r"(a[1]), "r"(a[2]), "r"(a[3]), "r"(b[0]), "r"(b[1]));
}

// ---------------- Kernel 1: group sites by channel, build 2-site tiles ----------------
__global__ void prep_kernel(const void* __restrict__ chan_raw) {
    __shared__ int cnt[NCH], start[NCH], cur[NCH], tstart[NCH];
    __shared__ int is64;
    int t = threadIdx.x;                     // 256 threads
    if (t < NCH) cnt[t] = 0;
    for (int i = t; i < MAX_TILES; i += 256) g_tile_ch[i] = -1;
    if (t == 0) {                            // sniff dtype: int64 channels -> odd 32-bit words are 0
        const int* w32 = (const int*)chan_raw;
        int z = 0;
        for (int i = 1; i < 512; i += 2) z += (w32[i] == 0);
        is64 = (z > 128);
        g_is64 = is64;
    }
    __syncthreads();
    const long long* c64 = (const long long*)chan_raw;
    const int*       c32 = (const int*)chan_raw;
    for (int l = t; l < L_DIM; l += 256) {
        int c = (is64 ? (int)c64[l] : c32[l]) & (NCH - 1);
        atomicAdd(&cnt[c], 1);
    }
    __syncthreads();
    if (t == 0) {
        int s = 0, ts = 0;
        for (int g = 0; g < NCH; g++) {
            start[g] = s; cur[g] = s; tstart[g] = ts;
            s += cnt[g]; ts += (cnt[g] + 1) >> 1;
        }
    }
    __syncthreads();
    for (int l = t; l < L_DIM; l += 256) {
        int c = (is64 ? (int)c64[l] : c32[l]) & (NCH - 1);
        int p = atomicAdd(&cur[c], 1);
        g_sorted[p] = l;
    }
    __syncthreads();
    if (t < NCH) {
        int g = t, s0 = start[g], c = cnt[g], ts = tstart[g];
        for (int i = 0; i < (c + 1) / 2; i++) {
            g_tile_l0[ts + i] = g_sorted[s0 + 2 * i];
            g_tile_l1[ts + i] = (2 * i + 1 < c) ? g_sorted[s0 + 2 * i + 1] : -1;
            g_tile_ch[ts + i] = g;
        }
    }
}

// ---------------- Kernel 2: per-tile mma.sync tf32 GEMM + fused epilogue ----------------
// A = W[ch] (M=128 Cout rows, K=128), B = X tile (N=128 site-rows: cols 0..63 -> l0, 64..127 -> l1)
// Warp w computes rows [32w, 32w+32) x all 128 cols.
static constexpr int SROW = 132;                        // padded row stride (floats)
static constexpr int BIAS_OFF = 0;                      // 128 floats
static constexpr int W_OFF = 512;                       // bytes
static constexpr int X_OFF = W_OFF + C_DIM * SROW * 4;  // bytes
static constexpr int SMEM_TOTAL = X_OFF + C_DIM * SROW * 4;  // ~136 KB

__global__ void __launch_bounds__(128, 1) dense_kernel(
    const float* __restrict__ x, const float* __restrict__ weight,
    const float* __restrict__ bias, float* __restrict__ out)
{
    int tile = blockIdx.x;
    int ch = g_tile_ch[tile];
    if (ch < 0) return;
    int l0 = g_tile_l0[tile], l1 = g_tile_l1[tile];

    extern __shared__ char smem[];
    float* sbias = reinterpret_cast<float*>(smem + BIAS_OFF);
    float* Ws    = reinterpret_cast<float*>(smem + W_OFF);
    float* Xs    = reinterpret_cast<float*>(smem + X_OFF);

    int tid = threadIdx.x, wid = tid >> 5, lane = tid & 31;
    int lr = lane >> 2, lc = lane & 3;

    // ---- load phase ----
    sbias[tid] = bias[ch * C_DIM + tid];
    const float4* Wsrc = reinterpret_cast<const float4*>(weight + (size_t)ch * (C_DIM * C_DIM));
    #pragma unroll
    for (int i = 0; i < 32; i++) {
        int f = tid + (i << 7);                 // 0..4095 float4s
        float4 v = Wsrc[f];
        v.x = rtf32_f(v.x); v.y = rtf32_f(v.y); v.z = rtf32_f(v.z); v.w = rtf32_f(v.w);
        int row = f >> 5, k4 = (f & 31) << 2;
        *reinterpret_cast<float4*>(Ws + row * SROW + k4) = v;
    }
    #pragma unroll
    for (int h = 0; h < 2; h++) {
        int l = h ? l1 : l0;
        #pragma unroll
        for (int i = 0; i < 16; i++) {
            int f = tid + (i << 7);             // 0..2047 float4s
            int b = f >> 5, k4 = (f & 31) << 2;
            float4 v = make_float4(0.f, 0.f, 0.f, 0.f);
            if (l >= 0)
                v = *reinterpret_cast<const float4*>(x + ((size_t)b * L_DIM + l) * C_DIM + k4);
            *reinterpret_cast<float4*>(Xs + (h * 64 + b) * SROW + k4) = v;  // raw fp32 (exact residual)
        }
    }
    __syncthreads();

    // ---- MMA phase: 2 m-frags x 16 n-frags, 16 k-steps of 8 ----
    float acc[2][16][4];
    #pragma unroll
    for (int mf = 0; mf < 2; mf++)
        #pragma unroll
        for (int nf = 0; nf < 16; nf++)
            #pragma unroll
            for (int j = 0; j < 4; j++) acc[mf][nf][j] = 0.f;

    const uint32_t* Wu = reinterpret_cast<const uint32_t*>(Ws);
    #pragma unroll
    for (int ks = 0; ks < 16; ks++) {
        int k = ks << 3;
        uint32_t bf[16][2];
        #pragma unroll
        for (int nf = 0; nf < 16; nf++) {
            const float* p = Xs + (nf * 8 + lr) * SROW + k + lc;
            bf[nf][0] = rtf32_u(p[0]);
            bf[nf][1] = rtf32_u(p[4]);
        }
        uint32_t af[2][4];
        #pragma unroll
        for (int mf = 0; mf < 2; mf++) {
            const uint32_t* p = Wu + (wid * 32 + mf * 16 + lr) * SROW + k + lc;
            af[mf][0] = p[0];
            af[mf][1] = p[8 * SROW];
            af[mf][2] = p[4];
            af[mf][3] = p[8 * SROW + 4];
        }
        #pragma unroll
        for (int mf = 0; mf < 2; mf++)
            #pragma unroll
            for (int nf = 0; nf < 16; nf++)
                mma_tf32(acc[mf][nf], af[mf], bf[nf]);
    }
    __syncthreads();          // all warps done reading Ws before staging overwrites it

    // ---- epilogue: stage C to smem [col][o], then coalesced fused store ----
    float* Cs = Ws;
    #pragma unroll
    for (int mf = 0; mf < 2; mf++) {
        int row = wid * 32 + mf * 16 + lr;
        #pragma unroll
        for (int nf = 0; nf < 16; nf++) {
            int col = nf * 8 + lc * 2;
            Cs[col * SROW + row]           = acc[mf][nf][0];
            Cs[(col + 1) * SROW + row]     = acc[mf][nf][1];
            Cs[col * SROW + row + 8]       = acc[mf][nf][2];
            Cs[(col + 1) * SROW + row + 8] = acc[mf][nf][3];
        }
    }
    __syncthreads();

    #pragma unroll
    for (int i = 0; i < 32; i++) {
        int f = tid + (i << 7);
        int col = f >> 5, o4 = (f & 31) << 2;
        int l = (col >= 64) ? l1 : l0;
        if (l < 0) continue;
        int b = col & 63;
        float4 a  = *reinterpret_cast<const float4*>(Cs + col * SROW + o4);
        float4 xv = *reinterpret_cast<const float4*>(Xs + col * SROW + o4);
        float4 bb = *reinterpret_cast<const float4*>(sbias + o4);
        float4 r;
        r.x = tanh_fast(a.x + bb.x) + xv.x;
        r.y = tanh_fast(a.y + bb.y) + xv.y;
        r.z = tanh_fast(a.z + bb.z) + xv.z;
        r.w = tanh_fast(a.w + bb.w) + xv.w;
        *reinterpret_cast<float4*>(out + ((size_t)b * L_DIM + l) * C_DIM + o4) = r;
    }
}

// ---------------- tail: channels passthrough CONVERTED TO FLOAT ----------------
// d_out is a single float32 buffer holding the flattened tuple (y, channels).
// Channels (ints 0..63, exactly representable) are written as float values
// right after y. Input width (int64 vs int32) is sniffed.
__global__ void tail_copy(const void* __restrict__ chan_raw, float* __restrict__ dst) {
    int i = blockIdx.x * 256 + threadIdx.x;
    if (i >= L_DIM) return;
    long long v = g_is64 ? ((const long long*)chan_raw)[i]
                         : (long long)((const int*)chan_raw)[i];
    dst[i] = (float)v;
}

extern "C" void kernel_launch(void* const* d_in, const int* in_sizes, int n_in,
                              void* d_out, int out_size) {
    const float* x  = (const float*)d_in[0];
    const void*  ch = d_in[1];
    const float* w  = (const float*)d_in[2];
    const float* b  = (const float*)d_in[3];
    float* out = (float*)d_out;

    cudaFuncSetAttribute(dense_kernel, cudaFuncAttributeMaxDynamicSharedMemorySize, SMEM_TOTAL);

    prep_kernel<<<1, 256>>>(ch);
    dense_kernel<<<MAX_TILES, 128, SMEM_TOTAL>>>(x, w, b, out);

    const long long Y_ELEMS = (long long)B_DIM * L_DIM * C_DIM;   // 67,108,864 fp32 = 256 MB
    tail_copy<<<(L_DIM + 255) / 256, 256>>>(ch, out + Y_ELEMS);
}

// round 6
// speedup vs baseline: 1.1054x; 1.1054x over previous
#include <cuda_runtime.h>
#include <cstdint>

#define B_DIM 64
#define L_DIM 8192
#define C_DIM 128
#define NCH   64
#define MAX_TILES 4160   // multiple of TPC; >= sum ceil(cnt/2)
#define TPC 4            // tiles per CTA

static __device__ int g_sorted[L_DIM];
static __device__ int g_tile_l0[MAX_TILES];
static __device__ int g_tile_l1[MAX_TILES];
static __device__ int g_tile_ch[MAX_TILES];
static __device__ int g_is64;
static __device__ int g_cnt[NCH], g_start[NCH], g_cur[NCH], g_tstart[NCH];

// ---------------- helpers ----------------
__device__ __forceinline__ uint32_t rtf32_u(float v) {   // fp32 -> tf32 RN
    uint32_t r; asm("cvt.rna.tf32.f32 %0, %1;" : "=r"(r) : "f"(v)); return r;
}
__device__ __forceinline__ float rtf32_f(float v) { return __uint_as_float(rtf32_u(v)); }
__device__ __forceinline__ float tanh_fast(float v) {
    float r; asm("tanh.approx.f32 %0, %1;" : "=f"(r) : "f"(v)); return r;
}
__device__ __forceinline__ void mma_tf32(float* d, const uint32_t* a, const uint32_t* b) {
    asm volatile(
        "mma.sync.aligned.m16n8k8.row.col.f32.tf32.tf32.f32 "
        "{%0,%1,%2,%3}, {%4,%5,%6,%7}, {%8,%9}, {%0,%1,%2,%3};"
        : "+f"(d[0]), "+f"(d[1]), "+f"(d[2]), "+f"(d[3])
        : "r"(a[0]), "r"(a[1]), "r"(a[2]), "r"(a[3]), "r"(b[0]), "r"(b[1]));
}
__device__ __forceinline__ void cp_async16(void* dst_smem, const void* src) {
    uint32_t d = (uint32_t)__cvta_generic_to_shared(dst_smem);
    asm volatile("cp.async.cg.shared.global [%0], [%1], 16;" :: "r"(d), "l"(src) : "memory");
}
#define CP_COMMIT() asm volatile("cp.async.commit_group;" ::: "memory")
#define CP_WAIT1()  asm volatile("cp.async.wait_group 1;" ::: "memory")

__device__ __forceinline__ int load_chan(const void* chan_raw, int l) {
    return (g_is64 ? (int)((const long long*)chan_raw)[l]
                   : ((const int*)chan_raw)[l]) & (NCH - 1);
}

// ---------------- prep: parallel counting sort + tile build ----------------
__global__ void prep_clear(const void* __restrict__ chan_raw) {   // grid 18 x 256
    int b = blockIdx.x, t = threadIdx.x;
    if (b < 17) {
        int i = b * 256 + t;
        if (i < MAX_TILES) g_tile_ch[i] = -1;
        if (b == 0 && t < NCH) g_cnt[t] = 0;
    } else {
        // dtype sniff: int64 channels -> odd 32-bit words are all zero
        __shared__ int votes[4];
        const int* w32 = (const int*)chan_raw;
        int z = (t < 128) ? (w32[2 * t + 1] == 0) : 0;
        unsigned m = __ballot_sync(0xFFFFFFFF, z);
        if ((t & 31) == 0) votes[t >> 5] = __popc(m);
        __syncthreads();
        if (t == 0) g_is64 = (votes[0] + votes[1] + votes[2] + votes[3]) > 64;
    }
}
__global__ void prep_hist(const void* __restrict__ chan_raw) {    // grid 32 x 256
    int l = blockIdx.x * 256 + threadIdx.x;
    atomicAdd(&g_cnt[load_chan(chan_raw, l)], 1);
}
__global__ void prep_prefix() {                                    // 1 x 1
    int s = 0, ts = 0;
    for (int g = 0; g < NCH; g++) {
        g_start[g] = s; g_cur[g] = s; g_tstart[g] = ts;
        s += g_cnt[g]; ts += (g_cnt[g] + 1) >> 1;
    }
}
__global__ void prep_scatter(const void* __restrict__ chan_raw) { // grid 32 x 256
    int l = blockIdx.x * 256 + threadIdx.x;
    int c = load_chan(chan_raw, l);
    int p = atomicAdd(&g_cur[c], 1);
    g_sorted[p] = l;
}
__global__ void prep_tiles() {                                     // grid 64 x 64
    int g = blockIdx.x;
    int s0 = g_start[g], c = g_cnt[g], ts = g_tstart[g];
    for (int i = threadIdx.x; i < (c + 1) / 2; i += 64) {
        g_tile_l0[ts + i] = g_sorted[s0 + 2 * i];
        g_tile_l1[ts + i] = (2 * i + 1 < c) ? g_sorted[s0 + 2 * i + 1] : -1;
        g_tile_ch[ts + i] = g;
    }
}

// ---------------- dense: multi-tile CTA, W resident, double-buffered X ----------------
static constexpr int SROW = 132;                               // padded row stride (floats)
static constexpr int WBYTES = C_DIM * SROW * 4;                // 67584
static constexpr int BIAS_OFF = 0;                             // 512 B
static constexpr int W_OFF  = 512;
static constexpr int X0_OFF = W_OFF + WBYTES;
static constexpr int X1_OFF = X0_OFF + WBYTES;
static constexpr int CS_OFF = X1_OFF + WBYTES;                 // 32 cols staging
static constexpr int SMEM_TOTAL = CS_OFF + 32 * SROW * 4;      // 220160 B

__device__ __forceinline__ void prefetch_x(float* Xbuf, const float* __restrict__ x,
                                           int l0, int l1, int tid) {
    #pragma unroll
    for (int h = 0; h < 2; h++) {
        int l = h ? l1 : l0;
        if (l < 0) continue;
        #pragma unroll
        for (int i = 0; i < 16; i++) {
            int f = tid + (i << 7);
            int b = f >> 5, k4 = (f & 31) << 2;
            cp_async16(Xbuf + (h * 64 + b) * SROW + k4,
                       x + ((size_t)b * L_DIM + l) * C_DIM + k4);
        }
    }
}
__device__ __forceinline__ void load_w(float* Ws, float* sbias,
                                       const float* __restrict__ weight,
                                       const float* __restrict__ bias, int ch, int tid) {
    sbias[tid] = bias[ch * C_DIM + tid];
    const float4* Wsrc = reinterpret_cast<const float4*>(weight + (size_t)ch * (C_DIM * C_DIM));
    #pragma unroll
    for (int i = 0; i < 32; i++) {
        int f = tid + (i << 7);
        float4 v = Wsrc[f];
        v.x = rtf32_f(v.x); v.y = rtf32_f(v.y); v.z = rtf32_f(v.z); v.w = rtf32_f(v.w);
        *reinterpret_cast<float4*>(Ws + (f >> 5) * SROW + ((f & 31) << 2)) = v;
    }
}

__global__ void __launch_bounds__(128, 1) dense_kernel(
    const float* __restrict__ x, const float* __restrict__ weight,
    const float* __restrict__ bias, float* __restrict__ out)
{
    int base = blockIdx.x * TPC;
    int ch0 = g_tile_ch[base];
    if (ch0 < 0) return;

    extern __shared__ char smem[];
    float* sbias = reinterpret_cast<float*>(smem + BIAS_OFF);
    float* Ws    = reinterpret_cast<float*>(smem + W_OFF);
    float* Xb[2] = { reinterpret_cast<float*>(smem + X0_OFF),
                     reinterpret_cast<float*>(smem + X1_OFF) };
    float* Cs    = reinterpret_cast<float*>(smem + CS_OFF);

    int tid = threadIdx.x, wid = tid >> 5, lane = tid & 31;
    int lr = lane >> 2, lc = lane & 3;

    // prefetch X(0); overlap W(ch0) load with it
    prefetch_x(Xb[0], x, g_tile_l0[base], g_tile_l1[base], tid);
    CP_COMMIT();
    load_w(Ws, sbias, weight, bias, ch0, tid);
    int cur_ch = ch0;

    for (int t = 0; t < TPC; t++) {
        int idx = base + t;
        int ch = g_tile_ch[idx];
        if (ch < 0) break;
        int l0 = g_tile_l0[idx], l1 = g_tile_l1[idx];

        if (ch != cur_ch) {
            __syncthreads();                     // prior tile fully done with Ws/sbias
            load_w(Ws, sbias, weight, bias, ch, tid);
            cur_ch = ch;
        }

        // prefetch X(t+1)
        if (t + 1 < TPC && g_tile_ch[idx + 1] >= 0)
            prefetch_x(Xb[(t + 1) & 1], x, g_tile_l0[idx + 1], g_tile_l1[idx + 1], tid);
        CP_COMMIT();

        CP_WAIT1();                              // X(t) landed (newest group may pend)
        __syncthreads();                         // X(t) + W visible CTA-wide

        const float* Xs = Xb[t & 1];
        const uint32_t* Xu = reinterpret_cast<const uint32_t*>(Xs);
        const uint32_t* Wu = reinterpret_cast<const uint32_t*>(Ws);

        // ---- MMA: 2 m-frags x 16 n-frags, 16 k-steps of 8; X fed as raw fp32 (HW tf32 trunc) ----
        float acc[2][16][4];
        #pragma unroll
        for (int mf = 0; mf < 2; mf++)
            #pragma unroll
            for (int nf = 0; nf < 16; nf++)
                #pragma unroll
                for (int j = 0; j < 4; j++) acc[mf][nf][j] = 0.f;

        #pragma unroll
        for (int ks = 0; ks < 16; ks++) {
            int k = ks << 3;
            uint32_t bf[16][2];
            #pragma unroll
            for (int nf = 0; nf < 16; nf++) {
                const uint32_t* p = Xu + (nf * 8 + lr) * SROW + k + lc;
                bf[nf][0] = p[0];
                bf[nf][1] = p[4];
            }
            uint32_t af[2][4];
            #pragma unroll
            for (int mf = 0; mf < 2; mf++) {
                const uint32_t* p = Wu + (wid * 32 + mf * 16 + lr) * SROW + k + lc;
                af[mf][0] = p[0];
                af[mf][1] = p[8 * SROW];
                af[mf][2] = p[4];
                af[mf][3] = p[8 * SROW + 4];
            }
            #pragma unroll
            for (int mf = 0; mf < 2; mf++)
                #pragma unroll
                for (int nf = 0; nf < 16; nf++)
                    mma_tf32(acc[mf][nf], af[mf], bf[nf]);
        }

        // ---- epilogue: 4 passes of 32 columns through Cs staging ----
        #pragma unroll
        for (int p = 0; p < 4; p++) {
            __syncthreads();                    // Cs free (prev pass readers done)
            #pragma unroll
            for (int mf = 0; mf < 2; mf++) {
                int row = wid * 32 + mf * 16 + lr;
                #pragma unroll
                for (int nfl = 0; nfl < 4; nfl++) {
                    int nf = p * 4 + nfl;
                    int cl = nfl * 8 + lc * 2;  // col within pass
                    Cs[cl * SROW + row]           = acc[mf][nf][0];
                    Cs[(cl + 1) * SROW + row]     = acc[mf][nf][1];
                    Cs[cl * SROW + row + 8]       = acc[mf][nf][2];
                    Cs[(cl + 1) * SROW + row + 8] = acc[mf][nf][3];
                }
            }
            __syncthreads();
            #pragma unroll
            for (int i = 0; i < 8; i++) {
                int f = i * 128 + tid;
                int cl = f >> 5, o4 = (f & 31) << 2;
                int col = p * 32 + cl;
                int l = (col >= 64) ? l1 : l0;
                if (l < 0) continue;
                int b = col & 63;
                float4 a  = *reinterpret_cast<const float4*>(Cs + cl * SROW + o4);
                float4 xv = *reinterpret_cast<const float4*>(Xs + col * SROW + o4);
                float4 bb = *reinterpret_cast<const float4*>(sbias + o4);
                float4 r;
                r.x = tanh_fast(a.x + bb.x) + xv.x;
                r.y = tanh_fast(a.y + bb.y) + xv.y;
                r.z = tanh_fast(a.z + bb.z) + xv.z;
                r.w = tanh_fast(a.w + bb.w) + xv.w;
                *reinterpret_cast<float4*>(out + ((size_t)b * L_DIM + l) * C_DIM + o4) = r;
            }
        }
        __syncthreads();                        // residual reads done before buf reuse
    }
}

// ---------------- tail: channels passthrough as float ----------------
__global__ void tail_copy(const void* __restrict__ chan_raw, float* __restrict__ dst) {
    int i = blockIdx.x * 256 + threadIdx.x;
    if (i >= L_DIM) return;
    long long v = g_is64 ? ((const long long*)chan_raw)[i]
                         : (long long)((const int*)chan_raw)[i];
    dst[i] = (float)v;
}

extern "C" void kernel_launch(void* const* d_in, const int* in_sizes, int n_in,
                              void* d_out, int out_size) {
    const float* x  = (const float*)d_in[0];
    const void*  ch = d_in[1];
    const float* w  = (const float*)d_in[2];
    const float* b  = (const float*)d_in[3];
    float* out = (float*)d_out;

    cudaFuncSetAttribute(dense_kernel, cudaFuncAttributeMaxDynamicSharedMemorySize, SMEM_TOTAL);

    prep_clear<<<18, 256>>>(ch);
    prep_hist<<<32, 256>>>(ch);
    prep_prefix<<<1, 1>>>();
    prep_scatter<<<32, 256>>>(ch);
    prep_tiles<<<64, 64>>>();

    dense_kernel<<<MAX_TILES / TPC, 128, SMEM_TOTAL>>>(x, w, b, out);

    const long long Y_ELEMS = (long long)B_DIM * L_DIM * C_DIM;   // 67,108,864 fp32
    tail_copy<<<(L_DIM + 255) / 256, 256>>>(ch, out + Y_ELEMS);
}

// round 7
// speedup vs baseline: 1.2034x; 1.0886x over previous
#include <cuda_runtime.h>
#include <cstdint>

#define B_DIM 64
#define L_DIM 8192
#define C_DIM 128
#define NCH   64
#define MAX_TILES 4160   // multiple of TPC; >= sum ceil(cnt/2)
#define TPC 4            // tiles per CTA

static __device__ int g_sorted[L_DIM];
static __device__ int g_tile_l0[MAX_TILES];
static __device__ int g_tile_l1[MAX_TILES];
static __device__ int g_tile_ch[MAX_TILES];
static __device__ int g_is64;
static __device__ int g_cnt[NCH], g_start[NCH], g_cur[NCH], g_tstart[NCH];

// ---------------- helpers ----------------
__device__ __forceinline__ float tanh_fast(float v) {
    float r; asm("tanh.approx.f32 %0, %1;" : "=f"(r) : "f"(v)); return r;
}
__device__ __forceinline__ void mma_tf32(float* d, const uint32_t* a, const uint32_t* b) {
    asm volatile(
        "mma.sync.aligned.m16n8k8.row.col.f32.tf32.tf32.f32 "
        "{%0,%1,%2,%3}, {%4,%5,%6,%7}, {%8,%9}, {%0,%1,%2,%3};"
        : "+f"(d[0]), "+f"(d[1]), "+f"(d[2]), "+f"(d[3])
        : "r"(a[0]), "r"(a[1]), "r"(a[2]), "r"(a[3]), "r"(b[0]), "r"(b[1]));
}
__device__ __forceinline__ void cp_async16(void* dst_smem, const void* src) {
    uint32_t d = (uint32_t)__cvta_generic_to_shared(dst_smem);
    asm volatile("cp.async.cg.shared.global [%0], [%1], 16;" :: "r"(d), "l"(src) : "memory");
}
#define CP_COMMIT() asm volatile("cp.async.commit_group;" ::: "memory")
#define CP_WAIT1()  asm volatile("cp.async.wait_group 1;" ::: "memory")

__device__ __forceinline__ int load_chan(const void* chan_raw, int l) {
    return (g_is64 ? (int)((const long long*)chan_raw)[l]
                   : ((const int*)chan_raw)[l]) & (NCH - 1);
}

// ---------------- prep: parallel counting sort + tile build ----------------
__global__ void prep_clear(const void* __restrict__ chan_raw) {   // grid 18 x 256
    int b = blockIdx.x, t = threadIdx.x;
    if (b < 17) {
        int i = b * 256 + t;
        if (i < MAX_TILES) g_tile_ch[i] = -1;
        if (b == 0 && t < NCH) g_cnt[t] = 0;
    } else {
        __shared__ int votes[4];
        const int* w32 = (const int*)chan_raw;
        int z = (t < 128) ? (w32[2 * t + 1] == 0) : 0;
        unsigned m = __ballot_sync(0xFFFFFFFF, z);
        if ((t & 31) == 0) votes[t >> 5] = __popc(m);
        __syncthreads();
        if (t == 0) g_is64 = (votes[0] + votes[1] + votes[2] + votes[3]) > 64;
    }
}
__global__ void prep_hist(const void* __restrict__ chan_raw) {    // grid 32 x 256
    int l = blockIdx.x * 256 + threadIdx.x;
    atomicAdd(&g_cnt[load_chan(chan_raw, l)], 1);
}
__global__ void prep_prefix() {                                    // 1 x 1
    int s = 0, ts = 0;
    for (int g = 0; g < NCH; g++) {
        g_start[g] = s; g_cur[g] = s; g_tstart[g] = ts;
        s += g_cnt[g]; ts += (g_cnt[g] + 1) >> 1;
    }
}
__global__ void prep_scatter(const void* __restrict__ chan_raw) { // grid 32 x 256
    int l = blockIdx.x * 256 + threadIdx.x;
    int c = load_chan(chan_raw, l);
    int p = atomicAdd(&g_cur[c], 1);
    g_sorted[p] = l;
}
__global__ void prep_tiles() {                                     // grid 64 x 64
    int g = blockIdx.x;
    int s0 = g_start[g], c = g_cnt[g], ts = g_tstart[g];
    for (int i = threadIdx.x; i < (c + 1) / 2; i += 64) {
        g_tile_l0[ts + i] = g_sorted[s0 + 2 * i];
        g_tile_l1[ts + i] = (2 * i + 1 < c) ? g_sorted[s0 + 2 * i + 1] : -1;
        g_tile_ch[ts + i] = g;
    }
}

// ---------------- dense: 256 threads, warps split N; direct-register epilogue ----------------
static constexpr int SROW = 132;                  // padded row stride (floats)
static constexpr int WBYTES = C_DIM * SROW * 4;   // 67584
static constexpr int W_OFF  = 0;
static constexpr int X0_OFF = WBYTES;
static constexpr int X1_OFF = 2 * WBYTES;
static constexpr int SMEM_TOTAL = 3 * WBYTES;     // 202752 B

__device__ __forceinline__ void prefetch_x(float* Xbuf, const float* __restrict__ x,
                                           int l0, int l1, int tid) {
    #pragma unroll
    for (int h = 0; h < 2; h++) {
        int l = h ? l1 : l0;
        if (l < 0) continue;
        #pragma unroll
        for (int i = 0; i < 8; i++) {
            int f = tid + (i << 8);                 // 0..2047 float4s
            int b = f >> 5, k4 = (f & 31) << 2;
            cp_async16(Xbuf + (h * 64 + b) * SROW + k4,
                       x + ((size_t)b * L_DIM + l) * C_DIM + k4);
        }
    }
}
// W copied raw (no rounding): HW truncates fp32->tf32 in the MMA.
__device__ __forceinline__ void load_w(float* Ws, const float* __restrict__ weight,
                                       int ch, int tid) {
    const float4* Wsrc = reinterpret_cast<const float4*>(weight + (size_t)ch * (C_DIM * C_DIM));
    #pragma unroll
    for (int i = 0; i < 16; i++) {
        int f = tid + (i << 8);                     // 0..4095 float4s
        float4 v = Wsrc[f];
        *reinterpret_cast<float4*>(Ws + (f >> 5) * SROW + ((f & 31) << 2)) = v;
    }
}

__global__ void __launch_bounds__(256, 1) dense_kernel(
    const float* __restrict__ x, const float* __restrict__ weight,
    const float* __restrict__ bias, float* __restrict__ out)
{
    int base = blockIdx.x * TPC;
    int ch0 = g_tile_ch[base];
    if (ch0 < 0) return;

    extern __shared__ char smem[];
    float* Ws    = reinterpret_cast<float*>(smem + W_OFF);
    float* Xb[2] = { reinterpret_cast<float*>(smem + X0_OFF),
                     reinterpret_cast<float*>(smem + X1_OFF) };

    int tid = threadIdx.x, wid = tid >> 5, lane = tid & 31;
    int lr = lane >> 2, lc = lane & 3;
    int warp_m = wid & 3, warp_n = wid >> 2;      // M-quadrant / N-half
    int wbase = warp_m * 32;                      // this warp's 32 output rows
    int n0 = warp_n * 64;                         // this warp's 64 site columns

    // prefetch X(0); overlap W(ch0) load
    prefetch_x(Xb[0], x, g_tile_l0[base], g_tile_l1[base], tid);
    CP_COMMIT();
    load_w(Ws, weight, ch0, tid);
    int cur_ch = ch0;

    // per-thread bias registers: rows wbase+mf*16+lr (+8)
    float bw[2][2];
    #pragma unroll
    for (int mf = 0; mf < 2; mf++) {
        bw[mf][0] = bias[ch0 * C_DIM + wbase + mf * 16 + lr];
        bw[mf][1] = bias[ch0 * C_DIM + wbase + mf * 16 + lr + 8];
    }

    for (int t = 0; t < TPC; t++) {
        int idx = base + t;
        int ch = g_tile_ch[idx];
        if (ch < 0) break;
        int l0 = g_tile_l0[idx], l1 = g_tile_l1[idx];

        if (ch != cur_ch) {                       // rare (tiles sorted by channel)
            load_w(Ws, weight, ch, tid);          // end-of-tile sync already passed
            #pragma unroll
            for (int mf = 0; mf < 2; mf++) {
                bw[mf][0] = bias[ch * C_DIM + wbase + mf * 16 + lr];
                bw[mf][1] = bias[ch * C_DIM + wbase + mf * 16 + lr + 8];
            }
            cur_ch = ch;
        }

        if (t + 1 < TPC && g_tile_ch[idx + 1] >= 0)
            prefetch_x(Xb[(t + 1) & 1], x, g_tile_l0[idx + 1], g_tile_l1[idx + 1], tid);
        CP_COMMIT();
        CP_WAIT1();                               // X(t) landed
        __syncthreads();                          // X(t) + W visible CTA-wide

        const float* Xs = Xb[t & 1];
        const uint32_t* Xu = reinterpret_cast<const uint32_t*>(Xs);
        const uint32_t* Wu = reinterpret_cast<const uint32_t*>(Ws);

        // ---- MMA: 2 m-frags x 8 n-frags (this warp's N-half), 16 k-steps ----
        float acc[2][8][4];
        #pragma unroll
        for (int mf = 0; mf < 2; mf++)
            #pragma unroll
            for (int nf = 0; nf < 8; nf++)
                #pragma unroll
                for (int j = 0; j < 4; j++) acc[mf][nf][j] = 0.f;

        #pragma unroll
        for (int ks = 0; ks < 16; ks++) {
            int k = ks << 3;
            uint32_t bf[8][2];
            #pragma unroll
            for (int nf = 0; nf < 8; nf++) {
                const uint32_t* p = Xu + (n0 + nf * 8 + lr) * SROW + k + lc;
                bf[nf][0] = p[0];
                bf[nf][1] = p[4];
            }
            uint32_t af[2][4];
            #pragma unroll
            for (int mf = 0; mf < 2; mf++) {
                const uint32_t* p = Wu + (wbase + mf * 16 + lr) * SROW + k + lc;
                af[mf][0] = p[0];
                af[mf][1] = p[8 * SROW];
                af[mf][2] = p[4];
                af[mf][3] = p[8 * SROW + 4];
            }
            #pragma unroll
            for (int mf = 0; mf < 2; mf++)
                #pragma unroll
                for (int nf = 0; nf < 8; nf++)
                    mma_tf32(acc[mf][nf], af[mf], bf[nf]);
        }

        // ---- direct epilogue: warp_n selects site; fuse bias+tanh+residual ----
        int l = warp_n ? l1 : l0;
        if (l >= 0) {
            float* obase = out + (size_t)l * C_DIM;
            #pragma unroll
            for (int mf = 0; mf < 2; mf++) {
                int o = wbase + mf * 16 + lr;
                #pragma unroll
                for (int nf = 0; nf < 8; nf++) {
                    int b = nf * 8 + lc * 2;          // batch index (col within half)
                    int colg = n0 + b;                // global col for residual smem
                    float x00 = Xs[colg * SROW + o];
                    float x10 = Xs[(colg + 1) * SROW + o];
                    float x01 = Xs[colg * SROW + o + 8];
                    float x11 = Xs[(colg + 1) * SROW + o + 8];
                    float* p0 = obase + (size_t)b * (L_DIM * C_DIM) + o;
                    float* p1 = obase + (size_t)(b + 1) * (L_DIM * C_DIM) + o;
                    p0[0] = tanh_fast(acc[mf][nf][0] + bw[mf][0]) + x00;
                    p1[0] = tanh_fast(acc[mf][nf][1] + bw[mf][0]) + x10;
                    p0[8] = tanh_fast(acc[mf][nf][2] + bw[mf][1]) + x01;
                    p1[8] = tanh_fast(acc[mf][nf][3] + bw[mf][1]) + x11;
                }
            }
        }
        __syncthreads();      // all reads of Ws/Xs done before next-iteration overwrites
    }
}

// ---------------- tail: channels passthrough as float ----------------
__global__ void tail_copy(const void* __restrict__ chan_raw, float* __restrict__ dst) {
    int i = blockIdx.x * 256 + threadIdx.x;
    if (i >= L_DIM) return;
    long long v = g_is64 ? ((const long long*)chan_raw)[i]
                         : (long long)((const int*)chan_raw)[i];
    dst[i] = (float)v;
}

extern "C" void kernel_launch(void* const* d_in, const int* in_sizes, int n_in,
                              void* d_out, int out_size) {
    const float* x  = (const float*)d_in[0];
    const void*  ch = d_in[1];
    const float* w  = (const float*)d_in[2];
    const float* b  = (const float*)d_in[3];
    float* out = (float*)d_out;

    cudaFuncSetAttribute(dense_kernel, cudaFuncAttributeMaxDynamicSharedMemorySize, SMEM_TOTAL);

    prep_clear<<<18, 256>>>(ch);
    prep_hist<<<32, 256>>>(ch);
    prep_prefix<<<1, 1>>>();
    prep_scatter<<<32, 256>>>(ch);
    prep_tiles<<<64, 64>>>();

    dense_kernel<<<MAX_TILES / TPC, 256, SMEM_TOTAL>>>(x, w, b, out);

    const long long Y_ELEMS = (long long)B_DIM * L_DIM * C_DIM;   // 67,108,864 fp32
    tail_copy<<<(L_DIM + 255) / 256, 256>>>(ch, out + Y_ELEMS);
}

// round 8
// speedup vs baseline: 1.2528x; 1.0411x over previous
#include <cuda_runtime.h>
#include <cstdint>

#define B_DIM 64
#define L_DIM 8192
#define C_DIM 128
#define NCH   64
#define MAX_TILES 4160   // multiple of TPC; >= sum ceil(cnt/2)
#define TPC 4            // tiles per CTA

static __device__ int g_sorted[L_DIM];
static __device__ int g_tile_l0[MAX_TILES];
static __device__ int g_tile_l1[MAX_TILES];
static __device__ int g_tile_ch[MAX_TILES];
static __device__ int g_is64;
static __device__ int g_cnt[NCH], g_start[NCH], g_cur[NCH], g_tstart[NCH];

// ---------------- helpers ----------------
__device__ __forceinline__ uint32_t smem_u32(const void* p) {
    uint32_t a;
    asm("{ .reg .u64 t; cvta.to.shared.u64 t, %1; cvt.u32.u64 %0, t; }" : "=r"(a) : "l"(p));
    return a;
}
__device__ __forceinline__ float tanh_fast(float v) {
    float r; asm("tanh.approx.f32 %0, %1;" : "=f"(r) : "f"(v)); return r;
}
__device__ __forceinline__ void mma_tf32(float* d, const uint32_t* a, const uint32_t* b) {
    asm volatile(
        "mma.sync.aligned.m16n8k8.row.col.f32.tf32.tf32.f32 "
        "{%0,%1,%2,%3}, {%4,%5,%6,%7}, {%8,%9}, {%0,%1,%2,%3};"
        : "+f"(d[0]), "+f"(d[1]), "+f"(d[2]), "+f"(d[3])
        : "r"(a[0]), "r"(a[1]), "r"(a[2]), "r"(a[3]), "r"(b[0]), "r"(b[1]));
}

#define MBARRIER_INIT(addr, cnt) \
    asm volatile("mbarrier.init.shared.b64 [%0], %1;" :: "r"((uint32_t)(addr)), "r"((uint32_t)(cnt)) : "memory")

#define MBARRIER_WAIT_PARITY(addr, par) do {                                            \
    uint32_t _m = (uint32_t)(addr); uint32_t _p = (uint32_t)(par); uint32_t _d;         \
    asm volatile("{ .reg .pred p; mbarrier.try_wait.parity.acquire.cta.shared::cta.b64 p, [%1], %2; selp.b32 %0,1,0,p; }" \
                 : "=r"(_d) : "r"(_m), "r"(_p) : "memory");                             \
    if (!_d) {                                                                          \
        asm volatile("{ .reg .pred P1; WL%=: mbarrier.try_wait.parity.acquire.cta.shared::cta.b64 P1, [%0], %1, 0x989680;" \
                     " @P1 bra.uni WD%=; bra.uni WL%=; WD%=: }" :: "r"(_m), "r"(_p) : "memory"); \
    }                                                                                   \
} while (0)

__device__ __forceinline__ int load_chan(const void* chan_raw, int l) {
    return (g_is64 ? (int)((const long long*)chan_raw)[l]
                   : ((const int*)chan_raw)[l]) & (NCH - 1);
}

// ---------------- prep: parallel counting sort + tile build ----------------
__global__ void prep_clear(const void* __restrict__ chan_raw) {   // grid 18 x 256
    int b = blockIdx.x, t = threadIdx.x;
    if (b < 17) {
        int i = b * 256 + t;
        if (i < MAX_TILES) g_tile_ch[i] = -1;
        if (b == 0 && t < NCH) g_cnt[t] = 0;
    } else {
        __shared__ int votes[4];
        const int* w32 = (const int*)chan_raw;
        int z = (t < 128) ? (w32[2 * t + 1] == 0) : 0;
        unsigned m = __ballot_sync(0xFFFFFFFF, z);
        if ((t & 31) == 0) votes[t >> 5] = __popc(m);
        __syncthreads();
        if (t == 0) g_is64 = (votes[0] + votes[1] + votes[2] + votes[3]) > 64;
    }
}
__global__ void prep_hist(const void* __restrict__ chan_raw) {    // grid 32 x 256
    int l = blockIdx.x * 256 + threadIdx.x;
    atomicAdd(&g_cnt[load_chan(chan_raw, l)], 1);
}
__global__ void prep_prefix() {                                    // 1 x 1
    int s = 0, ts = 0;
    for (int g = 0; g < NCH; g++) {
        g_start[g] = s; g_cur[g] = s; g_tstart[g] = ts;
        s += g_cnt[g]; ts += (g_cnt[g] + 1) >> 1;
    }
}
__global__ void prep_scatter(const void* __restrict__ chan_raw) { // grid 32 x 256
    int l = blockIdx.x * 256 + threadIdx.x;
    int c = load_chan(chan_raw, l);
    int p = atomicAdd(&g_cur[c], 1);
    g_sorted[p] = l;
}
__global__ void prep_tiles() {                                     // grid 64 x 64
    int g = blockIdx.x;
    int s0 = g_start[g], c = g_cnt[g], ts = g_tstart[g];
    for (int i = threadIdx.x; i < (c + 1) / 2; i += 64) {
        g_tile_l0[ts + i] = g_sorted[s0 + 2 * i];
        g_tile_l1[ts + i] = (2 * i + 1 < c) ? g_sorted[s0 + 2 * i + 1] : -1;
        g_tile_ch[ts + i] = g;
    }
}

// ---------------- dense kernel ----------------
static constexpr int SROW = 132;                  // padded row stride (floats)
static constexpr int WBYTES = C_DIM * SROW * 4;   // 67584
static constexpr int BIAS_OFF = 0;                // 512 B
static constexpr int MBAR_OFF = 512;              // 2 x 8 B
static constexpr int W_OFF  = 1024;
static constexpr int X0_OFF = W_OFF + WBYTES;     // 68608
static constexpr int X1_OFF = X0_OFF + WBYTES;    // 136192
static constexpr int CS_OFF = X1_OFF + WBYTES;    // 203776 (32-col staging)
static constexpr int SMEM_TOTAL = CS_OFF + 32 * SROW * 4;  // 220672 B

// Issue one 512B TMA bulk copy per X row (tid<128: h = tid>>6 selects site, b = tid&63).
// Each issuing thread arrives with expect_tx(512); rows of an absent site (l<0) arrive plain.
__device__ __forceinline__ void issue_x(float* Xbuf, uint32_t mbar,
                                        const float* __restrict__ x,
                                        int l0, int l1, int tid) {
    if (tid >= 128) return;
    int h = tid >> 6, b = tid & 63;
    int l = h ? l1 : l0;
    if (l >= 0) {
        uint32_t dst = smem_u32(Xbuf + (h * 64 + b) * SROW);
        const float* src = x + ((size_t)b * L_DIM + l) * C_DIM;
        asm volatile("mbarrier.arrive.expect_tx.shared.b64 _, [%0], %1;"
                     :: "r"(mbar), "r"(512u) : "memory");
        asm volatile("cp.async.bulk.shared::cluster.global.mbarrier::complete_tx::bytes "
                     "[%0], [%1], %2, [%3];"
                     :: "r"(dst), "l"(src), "r"(512u), "r"(mbar) : "memory");
    } else {
        asm volatile("mbarrier.arrive.shared.b64 _, [%0];" :: "r"(mbar) : "memory");
    }
}

// W copied raw (HW truncates fp32->tf32 in the MMA); bias to smem.
__device__ __forceinline__ void load_w(float* Ws, float* sbias,
                                       const float* __restrict__ weight,
                                       const float* __restrict__ bias, int ch, int tid) {
    if (tid < 128) sbias[tid] = bias[ch * C_DIM + tid];
    const float4* Wsrc = reinterpret_cast<const float4*>(weight + (size_t)ch * (C_DIM * C_DIM));
    #pragma unroll
    for (int i = 0; i < 16; i++) {
        int f = tid + (i << 8);                     // 0..4095 float4s
        float4 v = Wsrc[f];
        *reinterpret_cast<float4*>(Ws + (f >> 5) * SROW + ((f & 31) << 2)) = v;
    }
}

__global__ void __launch_bounds__(256, 1) dense_kernel(
    const float* __restrict__ x, const float* __restrict__ weight,
    const float* __restrict__ bias, float* __restrict__ out)
{
    int base = blockIdx.x * TPC;
    int ch0 = g_tile_ch[base];
    if (ch0 < 0) return;

    extern __shared__ char smem[];
    float* sbias = reinterpret_cast<float*>(smem + BIAS_OFF);
    float* Ws    = reinterpret_cast<float*>(smem + W_OFF);
    float* Xb[2] = { reinterpret_cast<float*>(smem + X0_OFF),
                     reinterpret_cast<float*>(smem + X1_OFF) };
    float* Cs    = reinterpret_cast<float*>(smem + CS_OFF);
    uint32_t mb[2] = { smem_u32(smem + MBAR_OFF), smem_u32(smem + MBAR_OFF + 8) };

    int tid = threadIdx.x, wid = tid >> 5, lane = tid & 31;
    int lr = lane >> 2, lc = lane & 3;
    int warp_m = wid & 3, warp_n = wid >> 2;      // M-quadrant / N-half
    int wbase = warp_m * 32;
    int n0 = warp_n * 64;

    if (tid == 0) { MBARRIER_INIT(mb[0], 128); MBARRIER_INIT(mb[1], 128); }
    __syncthreads();                               // mbarriers visible

    issue_x(Xb[0], mb[0], x, g_tile_l0[base], g_tile_l1[base], tid);
    load_w(Ws, sbias, weight, bias, ch0, tid);
    __syncthreads();                               // W + bias visible
    int cur_ch = ch0;

    for (int t = 0; t < TPC; t++) {
        int idx = base + t;
        int ch = g_tile_ch[idx];
        if (ch < 0) break;
        int l0 = g_tile_l0[idx], l1 = g_tile_l1[idx];

        if (ch != cur_ch) {                        // uniform branch (tiles sorted)
            load_w(Ws, sbias, weight, bias, ch, tid);
            __syncthreads();
            cur_ch = ch;
        }

        // prefetch X(t+1); prior phase of mb[(t+1)&1] provably complete (waited at t-1)
        if (t + 1 < TPC && g_tile_ch[idx + 1] >= 0)
            issue_x(Xb[(t + 1) & 1], mb[(t + 1) & 1], x,
                    g_tile_l0[idx + 1], g_tile_l1[idx + 1], tid);

        MBARRIER_WAIT_PARITY(mb[t & 1], (t >> 1) & 1);   // X(t) landed (acquire)

        const float* Xs = Xb[t & 1];
        const uint32_t* Xu = reinterpret_cast<const uint32_t*>(Xs);
        const uint32_t* Wu = reinterpret_cast<const uint32_t*>(Ws);

        // ---- MMA: 2 m-frags x 8 n-frags (warp's N-half), 16 k-steps of 8 ----
        float acc[2][8][4];
        #pragma unroll
        for (int mf = 0; mf < 2; mf++)
            #pragma unroll
            for (int nf = 0; nf < 8; nf++)
                #pragma unroll
                for (int j = 0; j < 4; j++) acc[mf][nf][j] = 0.f;

        #pragma unroll
        for (int ks = 0; ks < 16; ks++) {
            int k = ks << 3;
            uint32_t bf[8][2];
            #pragma unroll
            for (int nf = 0; nf < 8; nf++) {
                const uint32_t* p = Xu + (n0 + nf * 8 + lr) * SROW + k + lc;
                bf[nf][0] = p[0];
                bf[nf][1] = p[4];
            }
            uint32_t af[2][4];
            #pragma unroll
            for (int mf = 0; mf < 2; mf++) {
                const uint32_t* p = Wu + (wbase + mf * 16 + lr) * SROW + k + lc;
                af[mf][0] = p[0];
                af[mf][1] = p[8 * SROW];
                af[mf][2] = p[4];
                af[mf][3] = p[8 * SROW + 4];
            }
            #pragma unroll
            for (int mf = 0; mf < 2; mf++)
                #pragma unroll
                for (int nf = 0; nf < 8; nf++)
                    mma_tf32(acc[mf][nf], af[mf], bf[nf]);
        }

        // ---- staged epilogue: 4 passes of 32 cols; warp-contiguous STG.128 ----
        #pragma unroll
        for (int p = 0; p < 4; p++) {
            __syncthreads();                       // Cs free
            if (warp_n == (p >> 1)) {
                int nfo = (p & 1) * 4;
                #pragma unroll
                for (int mf = 0; mf < 2; mf++) {
                    int row = wbase + mf * 16 + lr;
                    #pragma unroll
                    for (int j = 0; j < 4; j++) {
                        int nf = nfo + j;
                        int cl = nf * 8 + lc * 2 - (p & 1) * 32;
                        Cs[cl * SROW + row]           = acc[mf][nf][0];
                        Cs[(cl + 1) * SROW + row]     = acc[mf][nf][1];
                        Cs[cl * SROW + row + 8]       = acc[mf][nf][2];
                        Cs[(cl + 1) * SROW + row + 8] = acc[mf][nf][3];
                    }
                }
            }
            __syncthreads();
            #pragma unroll
            for (int i = 0; i < 4; i++) {
                int colL = i * 8 + wid;            // each warp owns whole 512B rows
                int col = p * 32 + colL;
                int l = (col >= 64) ? l1 : l0;
                if (l < 0) continue;
                int b = col & 63;
                int o4 = lane << 2;
                float4 a  = *reinterpret_cast<const float4*>(Cs + colL * SROW + o4);
                float4 xv = *reinterpret_cast<const float4*>(Xs + col * SROW + o4);
                float4 bb = *reinterpret_cast<const float4*>(sbias + o4);
                float4 r;
                r.x = tanh_fast(a.x + bb.x) + xv.x;
                r.y = tanh_fast(a.y + bb.y) + xv.y;
                r.z = tanh_fast(a.z + bb.z) + xv.z;
                r.w = tanh_fast(a.w + bb.w) + xv.w;
                *reinterpret_cast<float4*>(out + ((size_t)b * L_DIM + l) * C_DIM + o4) = r;
            }
        }
        __syncthreads();                           // Xs reads done before reuse
    }
}

// ---------------- tail: channels passthrough as float ----------------
__global__ void tail_copy(const void* __restrict__ chan_raw, float* __restrict__ dst) {
    int i = blockIdx.x * 256 + threadIdx.x;
    if (i >= L_DIM) return;
    long long v = g_is64 ? ((const long long*)chan_raw)[i]
                         : (long long)((const int*)chan_raw)[i];
    dst[i] = (float)v;
}

extern "C" void kernel_launch(void* const* d_in, const int* in_sizes, int n_in,
                              void* d_out, int out_size) {
    const float* x  = (const float*)d_in[0];
    const void*  ch = d_in[1];
    const float* w  = (const float*)d_in[2];
    const float* b  = (const float*)d_in[3];
    float* out = (float*)d_out;

    cudaFuncSetAttribute(dense_kernel, cudaFuncAttributeMaxDynamicSharedMemorySize, SMEM_TOTAL);

    prep_clear<<<18, 256>>>(ch);
    prep_hist<<<32, 256>>>(ch);
    prep_prefix<<<1, 1>>>();
    prep_scatter<<<32, 256>>>(ch);
    prep_tiles<<<64, 64>>>();

    dense_kernel<<<MAX_TILES / TPC, 256, SMEM_TOTAL>>>(x, w, b, out);

    const long long Y_ELEMS = (long long)B_DIM * L_DIM * C_DIM;   // 67,108,864 fp32
    tail_copy<<<(L_DIM + 255) / 256, 256>>>(ch, out + Y_ELEMS);
}

// round 9
// speedup vs baseline: 1.4829x; 1.1836x over previous
#include <cuda_runtime.h>
#include <cuda_fp16.h>
#include <cstdint>

#define B_DIM 64
#define L_DIM 8192
#define C_DIM 128
#define NCH   64
#define MAX_TILES 4160   // multiple of TPC; >= sum ceil(cnt/2)
#define TPC 4            // tiles per CTA

static __device__ int g_sorted[L_DIM];
static __device__ int g_tile_l0[MAX_TILES];
static __device__ int g_tile_l1[MAX_TILES];
static __device__ int g_tile_ch[MAX_TILES];
static __device__ int g_is64;
static __device__ int g_cnt[NCH], g_start[NCH], g_cur[NCH], g_tstart[NCH];

// ---------------- helpers ----------------
__device__ __forceinline__ uint32_t smem_u32(const void* p) {
    uint32_t a;
    asm("{ .reg .u64 t; cvta.to.shared.u64 t, %1; cvt.u32.u64 %0, t; }" : "=r"(a) : "l"(p));
    return a;
}
__device__ __forceinline__ float tanh_fast(float v) {
    float r; asm("tanh.approx.f32 %0, %1;" : "=f"(r) : "f"(v)); return r;
}
__device__ __forceinline__ void mma_f16(float* d, const uint32_t* a, const uint32_t* b) {
    asm volatile(
        "mma.sync.aligned.m16n8k16.row.col.f32.f16.f16.f32 "
        "{%0,%1,%2,%3}, {%4,%5,%6,%7}, {%8,%9}, {%0,%1,%2,%3};"
        : "+f"(d[0]), "+f"(d[1]), "+f"(d[2]), "+f"(d[3])
        : "r"(a[0]), "r"(a[1]), "r"(a[2]), "r"(a[3]), "r"(b[0]), "r"(b[1]));
}

#define MBARRIER_INIT(addr, cnt) \
    asm volatile("mbarrier.init.shared.b64 [%0], %1;" :: "r"((uint32_t)(addr)), "r"((uint32_t)(cnt)) : "memory")

#define MBARRIER_WAIT_PARITY(addr, par) do {                                            \
    uint32_t _m = (uint32_t)(addr); uint32_t _p = (uint32_t)(par); uint32_t _d;         \
    asm volatile("{ .reg .pred p; mbarrier.try_wait.parity.acquire.cta.shared::cta.b64 p, [%1], %2; selp.b32 %0,1,0,p; }" \
                 : "=r"(_d) : "r"(_m), "r"(_p) : "memory");                             \
    if (!_d) {                                                                          \
        asm volatile("{ .reg .pred P1; WL%=: mbarrier.try_wait.parity.acquire.cta.shared::cta.b64 P1, [%0], %1, 0x989680;" \
                     " @P1 bra.uni WD%=; bra.uni WL%=; WD%=: }" :: "r"(_m), "r"(_p) : "memory"); \
    }                                                                                   \
} while (0)

__device__ __forceinline__ int load_chan(const void* chan_raw, int l) {
    return (g_is64 ? (int)((const long long*)chan_raw)[l]
                   : ((const int*)chan_raw)[l]) & (NCH - 1);
}

// ---------------- prep: parallel counting sort + tile build ----------------
__global__ void prep_clear(const void* __restrict__ chan_raw) {   // grid 18 x 256
    int b = blockIdx.x, t = threadIdx.x;
    if (b < 17) {
        int i = b * 256 + t;
        if (i < MAX_TILES) g_tile_ch[i] = -1;
        if (b == 0 && t < NCH) g_cnt[t] = 0;
    } else {
        __shared__ int votes[4];
        const int* w32 = (const int*)chan_raw;
        int z = (t < 128) ? (w32[2 * t + 1] == 0) : 0;
        unsigned m = __ballot_sync(0xFFFFFFFF, z);
        if ((t & 31) == 0) votes[t >> 5] = __popc(m);
        __syncthreads();
        if (t == 0) g_is64 = (votes[0] + votes[1] + votes[2] + votes[3]) > 64;
    }
}
__global__ void prep_hist(const void* __restrict__ chan_raw) {    // grid 32 x 256
    int l = blockIdx.x * 256 + threadIdx.x;
    atomicAdd(&g_cnt[load_chan(chan_raw, l)], 1);
}
__global__ void prep_prefix() {                                    // 1 x 1
    int s = 0, ts = 0;
    for (int g = 0; g < NCH; g++) {
        g_start[g] = s; g_cur[g] = s; g_tstart[g] = ts;
        s += g_cnt[g]; ts += (g_cnt[g] + 1) >> 1;
    }
}
__global__ void prep_scatter(const void* __restrict__ chan_raw) { // grid 32 x 256
    int l = blockIdx.x * 256 + threadIdx.x;
    int c = load_chan(chan_raw, l);
    int p = atomicAdd(&g_cur[c], 1);
    g_sorted[p] = l;
}
__global__ void prep_tiles() {                                     // grid 64 x 64
    int g = blockIdx.x;
    int s0 = g_start[g], c = g_cnt[g], ts = g_tstart[g];
    for (int i = threadIdx.x; i < (c + 1) / 2; i += 64) {
        g_tile_l0[ts + i] = g_sorted[s0 + 2 * i];
        g_tile_l1[ts + i] = (2 * i + 1 < c) ? g_sorted[s0 + 2 * i + 1] : -1;
        g_tile_ch[ts + i] = g;
    }
}

// ---------------- dense kernel (fp16 m16n8k16) ----------------
static constexpr int SROW  = 132;                 // fp32 staging row stride (floats)
static constexpr int SROWH = 136;                 // fp16 row stride (halfs); 68 words
static constexpr int XFBYTES = C_DIM * SROW * 4;  // 67584
static constexpr int WHBYTES = C_DIM * SROWH * 2; // 34816
static constexpr int BIAS_OFF = 0;                // 512 B
static constexpr int MBAR_OFF = 512;              // 2 x 8 B
static constexpr int WH_OFF  = 1024;
static constexpr int X0_OFF  = WH_OFF + WHBYTES;           // fp32 staging 0
static constexpr int X1_OFF  = X0_OFF + XFBYTES;           // fp32 staging 1
static constexpr int XH_OFF  = X1_OFF + XFBYTES;           // fp16 mma operand
static constexpr int CS_OFF  = XH_OFF + WHBYTES;           // 32-col fp32 staging
static constexpr int SMEM_TOTAL = CS_OFF + 32 * SROW * 4;  // 222720 B

// one 512B TMA bulk copy per X row (tid<128: h = tid>>6 site, b = tid&63)
__device__ __forceinline__ void issue_x(float* Xbuf, uint32_t mbar,
                                        const float* __restrict__ x,
                                        int l0, int l1, int tid) {
    if (tid >= 128) return;
    int h = tid >> 6, b = tid & 63;
    int l = h ? l1 : l0;
    if (l >= 0) {
        uint32_t dst = smem_u32(Xbuf + (h * 64 + b) * SROW);
        const float* src = x + ((size_t)b * L_DIM + l) * C_DIM;
        asm volatile("mbarrier.arrive.expect_tx.shared.b64 _, [%0], %1;"
                     :: "r"(mbar), "r"(512u) : "memory");
        asm volatile("cp.async.bulk.shared::cluster.global.mbarrier::complete_tx::bytes "
                     "[%0], [%1], %2, [%3];"
                     :: "r"(dst), "l"(src), "r"(512u), "r"(mbar) : "memory");
    } else {
        asm volatile("mbarrier.arrive.shared.b64 _, [%0];" :: "r"(mbar) : "memory");
    }
}

// W: LDG fp32 -> RN fp16 -> smem; bias -> smem fp32
__device__ __forceinline__ void load_w(__half* Wh, float* sbias,
                                       const float* __restrict__ weight,
                                       const float* __restrict__ bias, int ch, int tid) {
    if (tid < 128) sbias[tid] = bias[ch * C_DIM + tid];
    const float4* Wsrc = reinterpret_cast<const float4*>(weight + (size_t)ch * (C_DIM * C_DIM));
    #pragma unroll
    for (int i = 0; i < 16; i++) {
        int f = tid + (i << 8);                     // 0..4095 float4s
        float4 v = Wsrc[f];
        __half2 h0 = __floats2half2_rn(v.x, v.y);
        __half2 h1 = __floats2half2_rn(v.z, v.w);
        int row = f >> 5, k4 = (f & 31) << 2;
        *reinterpret_cast<uint2*>(Wh + row * SROWH + k4) =
            make_uint2(*(uint32_t*)&h0, *(uint32_t*)&h1);
    }
}

// convert fp32 staging tile -> fp16 operand tile (RN)
__device__ __forceinline__ void convert_x(const float* Xf, __half* Xh, int tid) {
    #pragma unroll
    for (int i = 0; i < 16; i++) {
        int f = tid + (i << 8);
        int row = f >> 5, k4 = (f & 31) << 2;
        float4 v = *reinterpret_cast<const float4*>(Xf + row * SROW + k4);
        __half2 h0 = __floats2half2_rn(v.x, v.y);
        __half2 h1 = __floats2half2_rn(v.z, v.w);
        *reinterpret_cast<uint2*>(Xh + row * SROWH + k4) =
            make_uint2(*(uint32_t*)&h0, *(uint32_t*)&h1);
    }
}

__global__ void __launch_bounds__(256, 1) dense_kernel(
    const float* __restrict__ x, const float* __restrict__ weight,
    const float* __restrict__ bias, float* __restrict__ out)
{
    int base = blockIdx.x * TPC;
    int ch0 = g_tile_ch[base];
    if (ch0 < 0) return;

    extern __shared__ char smem[];
    float*  sbias = reinterpret_cast<float*>(smem + BIAS_OFF);
    __half* Wh    = reinterpret_cast<__half*>(smem + WH_OFF);
    float*  Xf[2] = { reinterpret_cast<float*>(smem + X0_OFF),
                      reinterpret_cast<float*>(smem + X1_OFF) };
    __half* Xh    = reinterpret_cast<__half*>(smem + XH_OFF);
    float*  Cs    = reinterpret_cast<float*>(smem + CS_OFF);
    uint32_t mb[2] = { smem_u32(smem + MBAR_OFF), smem_u32(smem + MBAR_OFF + 8) };

    int tid = threadIdx.x, wid = tid >> 5, lane = tid & 31;
    int lr = lane >> 2, lc = lane & 3;
    int warp_m = wid & 3, warp_n = wid >> 2;      // M-quadrant / N-half
    int wbase = warp_m * 32;
    int n0 = warp_n * 64;

    if (tid == 0) { MBARRIER_INIT(mb[0], 128); MBARRIER_INIT(mb[1], 128); }
    __syncthreads();

    issue_x(Xf[0], mb[0], x, g_tile_l0[base], g_tile_l1[base], tid);
    load_w(Wh, sbias, weight, bias, ch0, tid);
    __syncthreads();                               // W + bias visible
    int cur_ch = ch0;

    for (int t = 0; t < TPC; t++) {
        int idx = base + t;
        int ch = g_tile_ch[idx];
        if (ch < 0) break;
        int l0 = g_tile_l0[idx], l1 = g_tile_l1[idx];

        if (ch != cur_ch) {                        // uniform branch (tiles sorted)
            load_w(Wh, sbias, weight, bias, ch, tid);
            __syncthreads();
            cur_ch = ch;
        }

        MBARRIER_WAIT_PARITY(mb[t & 1], (t >> 1) & 1);   // X(t) fp32 landed

        convert_x(Xf[t & 1], Xh, tid);             // prev tile fully done with Xh
        __syncthreads();                           // Xh ready CTA-wide

        // prefetch X(t+1) into the other staging buffer
        if (t + 1 < TPC && g_tile_ch[idx + 1] >= 0)
            issue_x(Xf[(t + 1) & 1], mb[(t + 1) & 1], x,
                    g_tile_l0[idx + 1], g_tile_l1[idx + 1], tid);

        const float* Xs = Xf[t & 1];               // exact fp32 residual source
        const uint32_t* Xu = reinterpret_cast<const uint32_t*>(Xh);
        const uint32_t* Wu = reinterpret_cast<const uint32_t*>(Wh);

        // ---- MMA: 2 m-frags x 8 n-frags, 8 k-steps of 16 (fp16) ----
        float acc[2][8][4];
        #pragma unroll
        for (int mf = 0; mf < 2; mf++)
            #pragma unroll
            for (int nf = 0; nf < 8; nf++)
                #pragma unroll
                for (int j = 0; j < 4; j++) acc[mf][nf][j] = 0.f;

        #pragma unroll
        for (int ks = 0; ks < 8; ks++) {
            int kw = ks * 8 + lc;                  // word offset within row (68-word rows)
            uint32_t bf[8][2];
            #pragma unroll
            for (int nf = 0; nf < 8; nf++) {
                const uint32_t* p = Xu + (n0 + nf * 8 + lr) * (SROWH / 2) + kw;
                bf[nf][0] = p[0];                  // (k=2lc,2lc+1 | n)
                bf[nf][1] = p[4];                  // (k=2lc+8,+9 | n)
            }
            uint32_t af[2][4];
            #pragma unroll
            for (int mf = 0; mf < 2; mf++) {
                const uint32_t* p = Wu + (wbase + mf * 16 + lr) * (SROWH / 2) + kw;
                af[mf][0] = p[0];                  // (row, k=2lc..)
                af[mf][1] = p[8 * (SROWH / 2)];    // (row+8, k=2lc..)
                af[mf][2] = p[4];                  // (row, k=2lc+8..)
                af[mf][3] = p[8 * (SROWH / 2) + 4];
            }
            #pragma unroll
            for (int mf = 0; mf < 2; mf++)
                #pragma unroll
                for (int nf = 0; nf < 8; nf++)
                    mma_f16(acc[mf][nf], af[mf], bf[nf]);
        }

        // ---- staged epilogue: 4 passes of 32 cols; warp-contiguous STG.128 ----
        #pragma unroll
        for (int p = 0; p < 4; p++) {
            __syncthreads();                       // Cs free
            if (warp_n == (p >> 1)) {
                int nfo = (p & 1) * 4;
                #pragma unroll
                for (int mf = 0; mf < 2; mf++) {
                    int row = wbase + mf * 16 + lr;
                    #pragma unroll
                    for (int j = 0; j < 4; j++) {
                        int nf = nfo + j;
                        int cl = nf * 8 + lc * 2 - (p & 1) * 32;
                        Cs[cl * SROW + row]           = acc[mf][nf][0];
                        Cs[(cl + 1) * SROW + row]     = acc[mf][nf][1];
                        Cs[cl * SROW + row + 8]       = acc[mf][nf][2];
                        Cs[(cl + 1) * SROW + row + 8] = acc[mf][nf][3];
                    }
                }
            }
            __syncthreads();
            #pragma unroll
            for (int i = 0; i < 4; i++) {
                int colL = i * 8 + wid;            // each warp owns whole 512B rows
                int col = p * 32 + colL;
                int l = (col >= 64) ? l1 : l0;
                if (l < 0) continue;
                int b = col & 63;
                int o4 = lane << 2;
                float4 a  = *reinterpret_cast<const float4*>(Cs + colL * SROW + o4);
                float4 xv = *reinterpret_cast<const float4*>(Xs + col * SROW + o4);
                float4 bb = *reinterpret_cast<const float4*>(sbias + o4);
                float4 r;
                r.x = tanh_fast(a.x + bb.x) + xv.x;
                r.y = tanh_fast(a.y + bb.y) + xv.y;
                r.z = tanh_fast(a.z + bb.z) + xv.z;
                r.w = tanh_fast(a.w + bb.w) + xv.w;
                *reinterpret_cast<float4*>(out + ((size_t)b * L_DIM + l) * C_DIM + o4) = r;
            }
        }
        __syncthreads();                           // Xs/Xh reads done before reuse
    }
}

// ---------------- tail: channels passthrough as float ----------------
__global__ void tail_copy(const void* __restrict__ chan_raw, float* __restrict__ dst) {
    int i = blockIdx.x * 256 + threadIdx.x;
    if (i >= L_DIM) return;
    long long v = g_is64 ? ((const long long*)chan_raw)[i]
                         : (long long)((const int*)chan_raw)[i];
    dst[i] = (float)v;
}

extern "C" void kernel_launch(void* const* d_in, const int* in_sizes, int n_in,
                              void* d_out, int out_size) {
    const float* x  = (const float*)d_in[0];
    const void*  ch = d_in[1];
    const float* w  = (const float*)d_in[2];
    const float* b  = (const float*)d_in[3];
    float* out = (float*)d_out;

    cudaFuncSetAttribute(dense_kernel, cudaFuncAttributeMaxDynamicSharedMemorySize, SMEM_TOTAL);

    prep_clear<<<18, 256>>>(ch);
    prep_hist<<<32, 256>>>(ch);
    prep_prefix<<<1, 1>>>();
    prep_scatter<<<32, 256>>>(ch);
    prep_tiles<<<64, 64>>>();

    dense_kernel<<<MAX_TILES / TPC, 256, SMEM_TOTAL>>>(x, w, b, out);

    const long long Y_ELEMS = (long long)B_DIM * L_DIM * C_DIM;   // 67,108,864 fp32
    tail_copy<<<(L_DIM + 255) / 256, 256>>>(ch, out + Y_ELEMS);
}

// round 10
// speedup vs baseline: 1.6729x; 1.1282x over previous
#include <cuda_runtime.h>
#include <cuda_fp16.h>
#include <cstdint>

#define B_DIM 64
#define L_DIM 8192
#define C_DIM 128
#define NCH   64
#define MAX_TILES 4160   // multiple of TPC; >= sum ceil(cnt/2)
#define TPC 4            // tiles per CTA

static __device__ int g_tile_l0[MAX_TILES];
static __device__ int g_tile_l1[MAX_TILES];
static __device__ int g_tile_ch[MAX_TILES];

// ---------------- helpers ----------------
__device__ __forceinline__ float tanh_fast(float v) {
    float r; asm("tanh.approx.f32 %0, %1;" : "=f"(r) : "f"(v)); return r;
}
__device__ __forceinline__ void mma_f16(float* d, const uint32_t* a, const uint32_t* b) {
    asm volatile(
        "mma.sync.aligned.m16n8k16.row.col.f32.f16.f16.f32 "
        "{%0,%1,%2,%3}, {%4,%5,%6,%7}, {%8,%9}, {%0,%1,%2,%3};"
        : "+f"(d[0]), "+f"(d[1]), "+f"(d[2]), "+f"(d[3])
        : "r"(a[0]), "r"(a[1]), "r"(a[2]), "r"(a[3]), "r"(b[0]), "r"(b[1]));
}

// ---------------- prep_all: one launch does everything ----------------
// counting sort by channel (smem), 2-site tile list, dtype sniff, and the
// channels-passthrough tail (written as float) — all in a single 1024-thread CTA.
__global__ void prep_all(const void* __restrict__ chan_raw, float* __restrict__ tail_out) {
    __shared__ int s_cnt[NCH], s_start[NCH], s_cur[NCH], s_ts[NCH];
    __shared__ int s_zcnt;
    extern __shared__ int s_sorted[];              // 8192 ints (32 KB dynamic)
    int t = threadIdx.x;                           // 1024 threads

    if (t == 0) s_zcnt = 0;
    if (t < NCH) s_cnt[t] = 0;
    for (int i = t; i < MAX_TILES; i += 1024) g_tile_ch[i] = -1;
    __syncthreads();

    // dtype sniff: int64 channels -> odd 32-bit words are zero
    if (t < 256) {
        const int* w32 = (const int*)chan_raw;
        int z = (w32[2 * t + 1] == 0);
        unsigned m = __ballot_sync(0xFFFFFFFF, z);
        if ((t & 31) == 0) atomicAdd(&s_zcnt, __popc(m));
    }
    __syncthreads();
    int is64 = s_zcnt > 128;

    const long long* c64 = (const long long*)chan_raw;
    const int*       c32 = (const int*)chan_raw;

    // histogram + tail write
    for (int i = t; i < L_DIM; i += 1024) {
        long long v = is64 ? c64[i] : (long long)c32[i];
        tail_out[i] = (float)v;
        atomicAdd(&s_cnt[(int)v & (NCH - 1)], 1);
    }
    __syncthreads();

    if (t == 0) {
        int s = 0, ts = 0;
        for (int g = 0; g < NCH; g++) {
            s_start[g] = s; s_cur[g] = s; s_ts[g] = ts;
            s += s_cnt[g]; ts += (s_cnt[g] + 1) >> 1;
        }
    }
    __syncthreads();

    // scatter
    for (int i = t; i < L_DIM; i += 1024) {
        int c = (int)(is64 ? c64[i] : (long long)c32[i]) & (NCH - 1);
        int p = atomicAdd(&s_cur[c], 1);
        s_sorted[p] = i;
    }
    __syncthreads();

    // tile build: 16 threads per channel
    int g = t >> 4, j = t & 15;
    int s0 = s_start[g], c = s_cnt[g], ts = s_ts[g];
    for (int i = j; i < (c + 1) / 2; i += 16) {
        g_tile_l0[ts + i] = s_sorted[s0 + 2 * i];
        g_tile_l1[ts + i] = (2 * i + 1 < c) ? s_sorted[s0 + 2 * i + 1] : -1;
        g_tile_ch[ts + i] = g;
    }
}

// ---------------- dense kernel (fp16 m16n8k16, 2 CTAs/SM) ----------------
static constexpr int SROW  = 132;                 // Cs fp32 row stride (floats)
static constexpr int SROWH = 136;                 // fp16 row stride (halfs) = 68 words
static constexpr int WHBYTES = C_DIM * SROWH * 2; // 34816
static constexpr int BIAS_OFF = 0;                // 512 B
static constexpr int WH_OFF  = 512;
static constexpr int XH0_OFF = WH_OFF + WHBYTES;            // 35328
static constexpr int XH1_OFF = XH0_OFF + WHBYTES;           // 70144
static constexpr int CS_OFF  = XH1_OFF + WHBYTES;           // 104960 (16-col staging)
static constexpr int SMEM_TOTAL = CS_OFF + 16 * SROW * 4;   // 113408 B -> 2 CTAs/SM

// X tile: LDG.128 fp32 -> RN fp16 -> STS (16 float4 / thread)
__device__ __forceinline__ void load_x(__half* Xh, const float* __restrict__ x,
                                       int l0, int l1, int tid) {
    #pragma unroll
    for (int i = 0; i < 16; i++) {
        int f = tid + (i << 8);                    // 0..4095 float4s
        int row = f >> 5, k4 = (f & 31) << 2;      // row uniform per warp
        int l = (row >= 64) ? l1 : l0;
        if (l < 0) continue;
        int b = row & 63;
        float4 v = *reinterpret_cast<const float4*>(x + ((size_t)b * L_DIM + l) * C_DIM + k4);
        __half2 h0 = __floats2half2_rn(v.x, v.y);
        __half2 h1 = __floats2half2_rn(v.z, v.w);
        *reinterpret_cast<uint2*>(Xh + row * SROWH + k4) =
            make_uint2(*(uint32_t*)&h0, *(uint32_t*)&h1);
    }
}
// W: LDG fp32 -> RN fp16 -> smem; bias -> smem fp32
__device__ __forceinline__ void load_w(__half* Wh, float* sbias,
                                       const float* __restrict__ weight,
                                       const float* __restrict__ bias, int ch, int tid) {
    if (tid < 128) sbias[tid] = bias[ch * C_DIM + tid];
    const float4* Wsrc = reinterpret_cast<const float4*>(weight + (size_t)ch * (C_DIM * C_DIM));
    #pragma unroll
    for (int i = 0; i < 16; i++) {
        int f = tid + (i << 8);
        float4 v = Wsrc[f];
        __half2 h0 = __floats2half2_rn(v.x, v.y);
        __half2 h1 = __floats2half2_rn(v.z, v.w);
        *reinterpret_cast<uint2*>(Wh + (f >> 5) * SROWH + ((f & 31) << 2)) =
            make_uint2(*(uint32_t*)&h0, *(uint32_t*)&h1);
    }
}

__global__ void __launch_bounds__(256, 2) dense_kernel(
    const float* __restrict__ x, const float* __restrict__ weight,
    const float* __restrict__ bias, float* __restrict__ out)
{
    int base = blockIdx.x * TPC;
    int ch0 = g_tile_ch[base];
    if (ch0 < 0) return;

    extern __shared__ char smem[];
    float*  sbias = reinterpret_cast<float*>(smem + BIAS_OFF);
    __half* Wh    = reinterpret_cast<__half*>(smem + WH_OFF);
    __half* Xh[2] = { reinterpret_cast<__half*>(smem + XH0_OFF),
                      reinterpret_cast<__half*>(smem + XH1_OFF) };
    float*  Cs    = reinterpret_cast<float*>(smem + CS_OFF);

    int tid = threadIdx.x, wid = tid >> 5, lane = tid & 31;
    int lr = lane >> 2, lc = lane & 3;
    int warp_m = wid & 3, warp_n = wid >> 2;      // M-quadrant / N-half
    int wbase = warp_m * 32;
    int n0 = warp_n * 64;

    load_x(Xh[0], x, g_tile_l0[base], g_tile_l1[base], tid);
    load_w(Wh, sbias, weight, bias, ch0, tid);
    __syncthreads();
    int cur_ch = ch0;

    for (int t = 0; t < TPC; t++) {
        int idx = base + t;
        int ch = g_tile_ch[idx];
        if (ch < 0) break;
        int l0 = g_tile_l0[idx], l1 = g_tile_l1[idx];

        if (ch != cur_ch) {                        // uniform (tiles channel-sorted)
            load_w(Wh, sbias, weight, bias, ch, tid);
            __syncthreads();
            cur_ch = ch;
        }

        const __half* Xhc = Xh[t & 1];
        const uint32_t* Xu = reinterpret_cast<const uint32_t*>(Xhc);
        const uint32_t* Wu = reinterpret_cast<const uint32_t*>(Wh);

        // ---- MMA: 2 m-frags x 8 n-frags, 8 k-steps of 16 ----
        float acc[2][8][4];
        #pragma unroll
        for (int mf = 0; mf < 2; mf++)
            #pragma unroll
            for (int nf = 0; nf < 8; nf++)
                #pragma unroll
                for (int j = 0; j < 4; j++) acc[mf][nf][j] = 0.f;

        #pragma unroll
        for (int ks = 0; ks < 8; ks++) {
            int kw = ks * 8 + lc;                  // word offset (68-word rows)
            uint32_t bf[8][2];
            #pragma unroll
            for (int nf = 0; nf < 8; nf++) {
                const uint32_t* p = Xu + (n0 + nf * 8 + lr) * (SROWH / 2) + kw;
                bf[nf][0] = p[0];
                bf[nf][1] = p[4];
            }
            uint32_t af[2][4];
            #pragma unroll
            for (int mf = 0; mf < 2; mf++) {
                const uint32_t* p = Wu + (wbase + mf * 16 + lr) * (SROWH / 2) + kw;
                af[mf][0] = p[0];
                af[mf][1] = p[8 * (SROWH / 2)];
                af[mf][2] = p[4];
                af[mf][3] = p[8 * (SROWH / 2) + 4];
            }
            #pragma unroll
            for (int mf = 0; mf < 2; mf++)
                #pragma unroll
                for (int nf = 0; nf < 8; nf++)
                    mma_f16(acc[mf][nf], af[mf], bf[nf]);
        }

        // ---- prefetch next X tile (LDG latency hides under epilogue) ----
        if (t + 1 < TPC && g_tile_ch[idx + 1] >= 0)
            load_x(Xh[(t + 1) & 1], x, g_tile_l0[idx + 1], g_tile_l1[idx + 1], tid);

        // ---- epilogue: 8 passes of 16 cols via Cs; residual from fp16 Xh ----
        float4 bb = *reinterpret_cast<const float4*>(sbias + (lane << 2));
        #pragma unroll
        for (int p = 0; p < 8; p++) {
            __syncthreads();                       // Cs free
            if (warp_n == (p >> 2)) {
                int nf0 = (p & 3) * 2;
                #pragma unroll
                for (int mf = 0; mf < 2; mf++) {
                    int row = wbase + mf * 16 + lr;
                    #pragma unroll
                    for (int j = 0; j < 2; j++) {
                        int nf = nf0 + j;
                        int cl = j * 8 + lc * 2;
                        Cs[cl * SROW + row]           = acc[mf][nf][0];
                        Cs[(cl + 1) * SROW + row]     = acc[mf][nf][1];
                        Cs[cl * SROW + row + 8]       = acc[mf][nf][2];
                        Cs[(cl + 1) * SROW + row + 8] = acc[mf][nf][3];
                    }
                }
            }
            __syncthreads();
            #pragma unroll
            for (int i = 0; i < 2; i++) {
                int colL = i * 8 + wid;            // 0..15; warp owns full rows
                int col = p * 16 + colL;
                int l = (col >= 64) ? l1 : l0;
                if (l < 0) continue;
                int b = col & 63;
                int o4 = lane << 2;
                float4 a = *reinterpret_cast<const float4*>(Cs + colL * SROW + o4);
                uint2 xr = *reinterpret_cast<const uint2*>(Xhc + col * SROWH + o4);
                float2 xlo = __half22float2(*reinterpret_cast<__half2*>(&xr.x));
                float2 xhi = __half22float2(*reinterpret_cast<__half2*>(&xr.y));
                float4 r;
                r.x = tanh_fast(a.x + bb.x) + xlo.x;
                r.y = tanh_fast(a.y + bb.y) + xlo.y;
                r.z = tanh_fast(a.z + bb.z) + xhi.x;
                r.w = tanh_fast(a.w + bb.w) + xhi.y;
                *reinterpret_cast<float4*>(out + ((size_t)b * L_DIM + l) * C_DIM + o4) = r;
            }
        }
        __syncthreads();   // prefetch STS + Xhc reads complete before next tile
    }
}

extern "C" void kernel_launch(void* const* d_in, const int* in_sizes, int n_in,
                              void* d_out, int out_size) {
    const float* x  = (const float*)d_in[0];
    const void*  ch = d_in[1];
    const float* w  = (const float*)d_in[2];
    const float* b  = (const float*)d_in[3];
    float* out = (float*)d_out;

    cudaFuncSetAttribute(dense_kernel, cudaFuncAttributeMaxDynamicSharedMemorySize, SMEM_TOTAL);
    cudaFuncSetAttribute(prep_all, cudaFuncAttributeMaxDynamicSharedMemorySize, L_DIM * 4);

    const long long Y_ELEMS = (long long)B_DIM * L_DIM * C_DIM;   // 67,108,864 fp32
    prep_all<<<1, 1024, L_DIM * 4>>>(ch, out + Y_ELEMS);
    dense_kernel<<<MAX_TILES / TPC, 256, SMEM_TOTAL>>>(x, w, b, out);
}

// round 11
// speedup vs baseline: 1.7506x; 1.0464x over previous
#include <cuda_runtime.h>
#include <cuda_fp16.h>
#include <cstdint>

#define B_DIM 64
#define L_DIM 8192
#define C_DIM 128
#define NCH   64
#define GRID_DENSE 296                 // 2 CTAs/SM x 148 SMs, exactly 1 wave
#define CHUNK 14                       // tiles per CTA
#define MAX_TILES (GRID_DENSE * CHUNK) // 4144 >= worst-case 4128 real tiles

static __device__ int g_tile_l0[MAX_TILES];
static __device__ int g_tile_l1[MAX_TILES];
static __device__ int g_tile_ch[MAX_TILES];

// ---------------- helpers ----------------
__device__ __forceinline__ float tanh_fast(float v) {
    float r; asm("tanh.approx.f32 %0, %1;" : "=f"(r) : "f"(v)); return r;
}
__device__ __forceinline__ void mma_f16(float* d, const uint32_t* a, const uint32_t* b) {
    asm volatile(
        "mma.sync.aligned.m16n8k16.row.col.f32.f16.f16.f32 "
        "{%0,%1,%2,%3}, {%4,%5,%6,%7}, {%8,%9}, {%0,%1,%2,%3};"
        : "+f"(d[0]), "+f"(d[1]), "+f"(d[2]), "+f"(d[3])
        : "r"(a[0]), "r"(a[1]), "r"(a[2]), "r"(a[3]), "r"(b[0]), "r"(b[1]));
}

// ---------------- prep_all: one launch does everything ----------------
__global__ void prep_all(const void* __restrict__ chan_raw, float* __restrict__ tail_out) {
    __shared__ int s_cnt[NCH], s_start[NCH], s_cur[NCH], s_ts[NCH];
    __shared__ int s_zcnt;
    extern __shared__ int s_sorted[];              // 8192 ints (32 KB dynamic)
    int t = threadIdx.x;                           // 1024 threads

    if (t == 0) s_zcnt = 0;
    if (t < NCH) s_cnt[t] = 0;
    for (int i = t; i < MAX_TILES; i += 1024) g_tile_ch[i] = -1;
    __syncthreads();

    // dtype sniff: int64 channels -> odd 32-bit words are zero
    if (t < 256) {
        const int* w32 = (const int*)chan_raw;
        int z = (w32[2 * t + 1] == 0);
        unsigned m = __ballot_sync(0xFFFFFFFF, z);
        if ((t & 31) == 0) atomicAdd(&s_zcnt, __popc(m));
    }
    __syncthreads();
    int is64 = s_zcnt > 128;

    const long long* c64 = (const long long*)chan_raw;
    const int*       c32 = (const int*)chan_raw;

    // histogram + channels tail (as float)
    for (int i = t; i < L_DIM; i += 1024) {
        long long v = is64 ? c64[i] : (long long)c32[i];
        tail_out[i] = (float)v;
        atomicAdd(&s_cnt[(int)v & (NCH - 1)], 1);
    }
    __syncthreads();

    if (t == 0) {
        int s = 0, ts = 0;
        for (int g = 0; g < NCH; g++) {
            s_start[g] = s; s_cur[g] = s; s_ts[g] = ts;
            s += s_cnt[g]; ts += (s_cnt[g] + 1) >> 1;
        }
    }
    __syncthreads();

    // scatter
    for (int i = t; i < L_DIM; i += 1024) {
        int c = (int)(is64 ? c64[i] : (long long)c32[i]) & (NCH - 1);
        int p = atomicAdd(&s_cur[c], 1);
        s_sorted[p] = i;
    }
    __syncthreads();

    // tile build: 16 threads per channel
    int g = t >> 4, j = t & 15;
    int s0 = s_start[g], c = s_cnt[g], ts = s_ts[g];
    for (int i = j; i < (c + 1) / 2; i += 16) {
        g_tile_l0[ts + i] = s_sorted[s0 + 2 * i];
        g_tile_l1[ts + i] = (2 * i + 1 < c) ? s_sorted[s0 + 2 * i + 1] : -1;
        g_tile_ch[ts + i] = g;
    }
}

// ---------------- dense kernel (fp16 m16n8k16, persistent, 2 CTAs/SM) ----------------
static constexpr int SROW  = 132;                 // Cs fp32 row stride (floats)
static constexpr int SROWH = 136;                 // fp16 row stride (halfs) = 68 words
static constexpr int WHBYTES = C_DIM * SROWH * 2; // 34816
static constexpr int BIAS_OFF = 0;                // 512 B
static constexpr int WH_OFF  = 512;
static constexpr int XH0_OFF = WH_OFF + WHBYTES;            // 35328
static constexpr int XH1_OFF = XH0_OFF + WHBYTES;           // 70144
static constexpr int CS_OFF  = XH1_OFF + WHBYTES;           // 104960 (16-col staging)
static constexpr int SMEM_TOTAL = CS_OFF + 16 * SROW * 4;   // 113408 B -> 2 CTAs/SM

// X tile: LDG.128 fp32 -> RN fp16 -> STS (16 float4 / thread)
__device__ __forceinline__ void load_x(__half* Xh, const float* __restrict__ x,
                                       int l0, int l1, int tid) {
    #pragma unroll
    for (int i = 0; i < 16; i++) {
        int f = tid + (i << 8);                    // 0..4095 float4s
        int row = f >> 5, k4 = (f & 31) << 2;      // row uniform per warp
        int l = (row >= 64) ? l1 : l0;
        if (l < 0) continue;
        int b = row & 63;
        float4 v = *reinterpret_cast<const float4*>(x + ((size_t)b * L_DIM + l) * C_DIM + k4);
        __half2 h0 = __floats2half2_rn(v.x, v.y);
        __half2 h1 = __floats2half2_rn(v.z, v.w);
        *reinterpret_cast<uint2*>(Xh + row * SROWH + k4) =
            make_uint2(*(uint32_t*)&h0, *(uint32_t*)&h1);
    }
}
// W: LDG fp32 -> RN fp16 -> smem; bias -> smem fp32
__device__ __forceinline__ void load_w(__half* Wh, float* sbias,
                                       const float* __restrict__ weight,
                                       const float* __restrict__ bias, int ch, int tid) {
    if (tid < 128) sbias[tid] = bias[ch * C_DIM + tid];
    const float4* Wsrc = reinterpret_cast<const float4*>(weight + (size_t)ch * (C_DIM * C_DIM));
    #pragma unroll
    for (int i = 0; i < 16; i++) {
        int f = tid + (i << 8);
        float4 v = Wsrc[f];
        __half2 h0 = __floats2half2_rn(v.x, v.y);
        __half2 h1 = __floats2half2_rn(v.z, v.w);
        *reinterpret_cast<uint2*>(Wh + (f >> 5) * SROWH + ((f & 31) << 2)) =
            make_uint2(*(uint32_t*)&h0, *(uint32_t*)&h1);
    }
}

__global__ void __launch_bounds__(256, 2) dense_kernel(
    const float* __restrict__ x, const float* __restrict__ weight,
    const float* __restrict__ bias, float* __restrict__ out)
{
    int base = blockIdx.x * CHUNK;
    int ch0 = g_tile_ch[base];
    if (ch0 < 0) return;

    extern __shared__ char smem[];
    float*  sbias = reinterpret_cast<float*>(smem + BIAS_OFF);
    __half* Wh    = reinterpret_cast<__half*>(smem + WH_OFF);
    __half* Xh[2] = { reinterpret_cast<__half*>(smem + XH0_OFF),
                      reinterpret_cast<__half*>(smem + XH1_OFF) };
    float*  Cs    = reinterpret_cast<float*>(smem + CS_OFF);

    int tid = threadIdx.x, wid = tid >> 5, lane = tid & 31;
    int lr = lane >> 2, lc = lane & 3;
    int warp_m = wid & 3, warp_n = wid >> 2;      // M-quadrant / N-half
    int wbase = warp_m * 32;
    int n0 = warp_n * 64;

    load_x(Xh[0], x, g_tile_l0[base], g_tile_l1[base], tid);
    load_w(Wh, sbias, weight, bias, ch0, tid);
    __syncthreads();
    int cur_ch = ch0;

    #pragma unroll 1
    for (int t = 0; t < CHUNK; t++) {
        int idx = base + t;
        int ch = g_tile_ch[idx];
        if (ch < 0) break;
        int l0 = g_tile_l0[idx], l1 = g_tile_l1[idx];

        if (ch != cur_ch) {                        // uniform (tiles channel-sorted)
            load_w(Wh, sbias, weight, bias, ch, tid);
            __syncthreads();
            cur_ch = ch;
        }

        const __half* Xhc = Xh[t & 1];
        const uint32_t* Xu = reinterpret_cast<const uint32_t*>(Xhc);
        const uint32_t* Wu = reinterpret_cast<const uint32_t*>(Wh);

        // ---- MMA: 2 m-frags x 8 n-frags, 8 k-steps of 16 ----
        float acc[2][8][4];
        #pragma unroll
        for (int mf = 0; mf < 2; mf++)
            #pragma unroll
            for (int nf = 0; nf < 8; nf++)
                #pragma unroll
                for (int j = 0; j < 4; j++) acc[mf][nf][j] = 0.f;

        #pragma unroll
        for (int ks = 0; ks < 8; ks++) {
            int kw = ks * 8 + lc;                  // word offset (68-word rows)
            uint32_t bf[8][2];
            #pragma unroll
            for (int nf = 0; nf < 8; nf++) {
                const uint32_t* p = Xu + (n0 + nf * 8 + lr) * (SROWH / 2) + kw;
                bf[nf][0] = p[0];
                bf[nf][1] = p[4];
            }
            uint32_t af[2][4];
            #pragma unroll
            for (int mf = 0; mf < 2; mf++) {
                const uint32_t* p = Wu + (wbase + mf * 16 + lr) * (SROWH / 2) + kw;
                af[mf][0] = p[0];
                af[mf][1] = p[8 * (SROWH / 2)];
                af[mf][2] = p[4];
                af[mf][3] = p[8 * (SROWH / 2) + 4];
            }
            #pragma unroll
            for (int mf = 0; mf < 2; mf++)
                #pragma unroll
                for (int nf = 0; nf < 8; nf++)
                    mma_f16(acc[mf][nf], af[mf], bf[nf]);
        }

        // ---- prefetch next X tile (LDG latency hides under epilogue) ----
        if (t + 1 < CHUNK && g_tile_ch[idx + 1] >= 0)
            load_x(Xh[(t + 1) & 1], x, g_tile_l0[idx + 1], g_tile_l1[idx + 1], tid);

        // ---- epilogue: 8 passes of 16 cols via Cs; residual from fp16 Xh ----
        float4 bb = *reinterpret_cast<const float4*>(sbias + (lane << 2));
        #pragma unroll
        for (int p = 0; p < 8; p++) {
            __syncthreads();                       // Cs free
            if (warp_n == (p >> 2)) {
                int nf0 = (p & 3) * 2;
                #pragma unroll
                for (int mf = 0; mf < 2; mf++) {
                    int row = wbase + mf * 16 + lr;
                    #pragma unroll
                    for (int j = 0; j < 2; j++) {
                        int nf = nf0 + j;
                        int cl = j * 8 + lc * 2;
                        Cs[cl * SROW + row]           = acc[mf][nf][0];
                        Cs[(cl + 1) * SROW + row]     = acc[mf][nf][1];
                        Cs[cl * SROW + row + 8]       = acc[mf][nf][2];
                        Cs[(cl + 1) * SROW + row + 8] = acc[mf][nf][3];
                    }
                }
            }
            __syncthreads();
            #pragma unroll
            for (int i = 0; i < 2; i++) {
                int colL = i * 8 + wid;            // 0..15; warp owns full rows
                int col = p * 16 + colL;
                int l = (col >= 64) ? l1 : l0;
                if (l < 0) continue;
                int b = col & 63;
                int o4 = lane << 2;
                float4 a = *reinterpret_cast<const float4*>(Cs + colL * SROW + o4);
                uint2 xr = *reinterpret_cast<const uint2*>(Xhc + col * SROWH + o4);
                float2 xlo = __half22float2(*reinterpret_cast<__half2*>(&xr.x));
                float2 xhi = __half22float2(*reinterpret_cast<__half2*>(&xr.y));
                float4 r;
                r.x = tanh_fast(a.x + bb.x) + xlo.x;
                r.y = tanh_fast(a.y + bb.y) + xlo.y;
                r.z = tanh_fast(a.z + bb.z) + xhi.x;
                r.w = tanh_fast(a.w + bb.w) + xhi.y;
                *reinterpret_cast<float4*>(out + ((size_t)b * L_DIM + l) * C_DIM + o4) = r;
            }
        }
        __syncthreads();   // prefetch STS + Xhc reads complete before next tile
    }
}

extern "C" void kernel_launch(void* const* d_in, const int* in_sizes, int n_in,
                              void* d_out, int out_size) {
    const float* x  = (const float*)d_in[0];
    const void*  ch = d_in[1];
    const float* w  = (const float*)d_in[2];
    const float* b  = (const float*)d_in[3];
    float* out = (float*)d_out;

    cudaFuncSetAttribute(dense_kernel, cudaFuncAttributeMaxDynamicSharedMemorySize, SMEM_TOTAL);
    cudaFuncSetAttribute(prep_all, cudaFuncAttributeMaxDynamicSharedMemorySize, L_DIM * 4);

    const long long Y_ELEMS = (long long)B_DIM * L_DIM * C_DIM;   // 67,108,864 fp32
    prep_all<<<1, 1024, L_DIM * 4>>>(ch, out + Y_ELEMS);
    dense_kernel<<<GRID_DENSE, 256, SMEM_TOTAL>>>(x, w, b, out);
}

// round 12
// speedup vs baseline: 1.7924x; 1.0239x over previous
#include <cuda_runtime.h>
#include <cuda_fp16.h>
#include <cstdint>

#define B_DIM 64
#define L_DIM 8192
#define C_DIM 128
#define NCH   64
#define GRID_DENSE 296                 // 2 CTAs/SM x 148 SMs, exactly 1 wave
#define CHUNK 14                       // tiles per CTA
#define MAX_TILES (GRID_DENSE * CHUNK) // 4144 >= worst-case 4128 real tiles

static __device__ int g_tile_l0[MAX_TILES];
static __device__ int g_tile_l1[MAX_TILES];
static __device__ int g_tile_ch[MAX_TILES];

// ---------------- helpers ----------------
__device__ __forceinline__ uint32_t smem_u32(const void* p) {
    uint32_t a;
    asm("{ .reg .u64 t; cvta.to.shared.u64 t, %1; cvt.u32.u64 %0, t; }" : "=r"(a) : "l"(p));
    return a;
}
__device__ __forceinline__ float tanh_fast(float v) {
    float r; asm("tanh.approx.f32 %0, %1;" : "=f"(r) : "f"(v)); return r;
}
__device__ __forceinline__ void mma_f16(float* d, const uint32_t* a, const uint32_t* b) {
    asm volatile(
        "mma.sync.aligned.m16n8k16.row.col.f32.f16.f16.f32 "
        "{%0,%1,%2,%3}, {%4,%5,%6,%7}, {%8,%9}, {%0,%1,%2,%3};"
        : "+f"(d[0]), "+f"(d[1]), "+f"(d[2]), "+f"(d[3])
        : "r"(a[0]), "r"(a[1]), "r"(a[2]), "r"(a[3]), "r"(b[0]), "r"(b[1]));
}
__device__ __forceinline__ void ldsm_x4(uint32_t* r, uint32_t addr) {
    asm volatile("ldmatrix.sync.aligned.m8n8.x4.shared.b16 {%0,%1,%2,%3}, [%4];"
        : "=r"(r[0]), "=r"(r[1]), "=r"(r[2]), "=r"(r[3]) : "r"(addr));
}

// ---------------- prep_all: one launch does everything ----------------
__global__ void prep_all(const void* __restrict__ chan_raw, float* __restrict__ tail_out) {
    __shared__ int s_cnt[NCH], s_start[NCH], s_cur[NCH], s_ts[NCH];
    __shared__ int s_zcnt;
    extern __shared__ int s_sorted[];              // 8192 ints (32 KB dynamic)
    int t = threadIdx.x;                           // 1024 threads

    if (t == 0) s_zcnt = 0;
    if (t < NCH) s_cnt[t] = 0;
    for (int i = t; i < MAX_TILES; i += 1024) g_tile_ch[i] = -1;
    __syncthreads();

    if (t < 256) {                                 // dtype sniff
        const int* w32 = (const int*)chan_raw;
        int z = (w32[2 * t + 1] == 0);
        unsigned m = __ballot_sync(0xFFFFFFFF, z);
        if ((t & 31) == 0) atomicAdd(&s_zcnt, __popc(m));
    }
    __syncthreads();
    int is64 = s_zcnt > 128;

    const long long* c64 = (const long long*)chan_raw;
    const int*       c32 = (const int*)chan_raw;

    for (int i = t; i < L_DIM; i += 1024) {        // histogram + channels tail
        long long v = is64 ? c64[i] : (long long)c32[i];
        tail_out[i] = (float)v;
        atomicAdd(&s_cnt[(int)v & (NCH - 1)], 1);
    }
    __syncthreads();

    if (t == 0) {
        int s = 0, ts = 0;
        for (int g = 0; g < NCH; g++) {
            s_start[g] = s; s_cur[g] = s; s_ts[g] = ts;
            s += s_cnt[g]; ts += (s_cnt[g] + 1) >> 1;
        }
    }
    __syncthreads();

    for (int i = t; i < L_DIM; i += 1024) {        // scatter
        int c = (int)(is64 ? c64[i] : (long long)c32[i]) & (NCH - 1);
        int p = atomicAdd(&s_cur[c], 1);
        s_sorted[p] = i;
    }
    __syncthreads();

    int g = t >> 4, j = t & 15;                    // tile build
    int s0 = s_start[g], c = s_cnt[g], ts = s_ts[g];
    for (int i = j; i < (c + 1) / 2; i += 16) {
        g_tile_l0[ts + i] = s_sorted[s0 + 2 * i];
        g_tile_l1[ts + i] = (2 * i + 1 < c) ? s_sorted[s0 + 2 * i + 1] : -1;
        g_tile_ch[ts + i] = g;
    }
}

// ---------------- dense kernel: ldmatrix + direct in-register epilogue ----------------
static constexpr int SROWH = 136;                 // fp16 row stride (halfs)
static constexpr int WHBYTES = C_DIM * SROWH * 2; // 34816
static constexpr int WH_OFF  = 0;
static constexpr int XH0_OFF = WHBYTES;
static constexpr int XH1_OFF = 2 * WHBYTES;
static constexpr int SMEM_TOTAL = 3 * WHBYTES;    // 104448 B -> 2 CTAs/SM

// X tile: LDG.128 fp32 -> RN fp16 -> STS.64
__device__ __forceinline__ void load_x(__half* Xh, const float* __restrict__ x,
                                       int l0, int l1, int tid) {
    #pragma unroll
    for (int i = 0; i < 16; i++) {
        int f = tid + (i << 8);                    // 0..4095 float4s
        int row = f >> 5, k4 = (f & 31) << 2;      // row uniform per warp
        int l = (row >= 64) ? l1 : l0;
        if (l < 0) continue;
        int b = row & 63;
        float4 v = *reinterpret_cast<const float4*>(x + ((size_t)b * L_DIM + l) * C_DIM + k4);
        __half2 h0 = __floats2half2_rn(v.x, v.y);
        __half2 h1 = __floats2half2_rn(v.z, v.w);
        *reinterpret_cast<uint2*>(Xh + row * SROWH + k4) =
            make_uint2(*(uint32_t*)&h0, *(uint32_t*)&h1);
    }
}
__device__ __forceinline__ void load_w(__half* Wh, const float* __restrict__ weight,
                                       int ch, int tid) {
    const float4* Wsrc = reinterpret_cast<const float4*>(weight + (size_t)ch * (C_DIM * C_DIM));
    #pragma unroll
    for (int i = 0; i < 16; i++) {
        int f = tid + (i << 8);
        float4 v = Wsrc[f];
        __half2 h0 = __floats2half2_rn(v.x, v.y);
        __half2 h1 = __floats2half2_rn(v.z, v.w);
        *reinterpret_cast<uint2*>(Wh + (f >> 5) * SROWH + ((f & 31) << 2)) =
            make_uint2(*(uint32_t*)&h0, *(uint32_t*)&h1);
    }
}

__global__ void __launch_bounds__(256, 2) dense_kernel(
    const float* __restrict__ x, const float* __restrict__ weight,
    const float* __restrict__ bias, float* __restrict__ out)
{
    int base = blockIdx.x * CHUNK;
    int ch0 = g_tile_ch[base];
    if (ch0 < 0) return;

    extern __shared__ char smem[];
    __half* Wh    = reinterpret_cast<__half*>(smem + WH_OFF);
    __half* Xh[2] = { reinterpret_cast<__half*>(smem + XH0_OFF),
                      reinterpret_cast<__half*>(smem + XH1_OFF) };

    int tid = threadIdx.x, wid = tid >> 5, lane = tid & 31;
    int lr = lane >> 2, lc = lane & 3;
    int warp_m = wid & 3, warp_n = wid >> 2;      // M-quadrant / N-half
    int wbase = warp_m * 32;
    int n0 = warp_n * 64;

    // ldmatrix per-thread address components
    int li = lane & 7, lg = lane >> 3;            // row-in-matrix, group
    // A: groups (g&1)->m-half, (g>>1)->k-half
    uint32_t aBase = smem_u32(Wh) +
        (uint32_t)(((wbase + (lg & 1) * 8 + li) * SROWH + (lg >> 1) * 8) * 2);
    // B: groups (g>>1)->n-half(within nf-pair), (g&1)->k-half
    uint32_t xoff = (uint32_t)(((n0 + (lg >> 1) * 8 + li) * SROWH + (lg & 1) * 8) * 2);
    uint32_t xBase[2] = { smem_u32(Xh[0]) + xoff, smem_u32(Xh[1]) + xoff };

    load_x(Xh[0], x, g_tile_l0[base], g_tile_l1[base], tid);
    load_w(Wh, weight, ch0, tid);
    int cur_ch = ch0;
    float br[2][2];                                // per-row bias in registers
    #pragma unroll
    for (int mf = 0; mf < 2; mf++) {
        br[mf][0] = bias[ch0 * C_DIM + wbase + mf * 16 + lr];
        br[mf][1] = bias[ch0 * C_DIM + wbase + mf * 16 + lr + 8];
    }

    #pragma unroll 1
    for (int t = 0; t < CHUNK; t++) {
        int idx = base + t;
        int ch = g_tile_ch[idx];
        if (ch < 0) break;
        int l0 = g_tile_l0[idx], l1 = g_tile_l1[idx];

        __syncthreads();                           // X(t) STS + prior-tile reads complete

        if (ch != cur_ch) {                        // uniform (channel-sorted tiles)
            load_w(Wh, weight, ch, tid);
            #pragma unroll
            for (int mf = 0; mf < 2; mf++) {
                br[mf][0] = bias[ch * C_DIM + wbase + mf * 16 + lr];
                br[mf][1] = bias[ch * C_DIM + wbase + mf * 16 + lr + 8];
            }
            cur_ch = ch;
            __syncthreads();
        }

        const __half* Xhc = Xh[t & 1];
        uint32_t bB = xBase[t & 1];

        // ---- MMA via ldmatrix: 2 m-frags x 8 n-frags, 8 k-steps of 16 ----
        float acc[2][8][4];
        #pragma unroll
        for (int mf = 0; mf < 2; mf++)
            #pragma unroll
            for (int nf = 0; nf < 8; nf++)
                #pragma unroll
                for (int j = 0; j < 4; j++) acc[mf][nf][j] = 0.f;

        #pragma unroll
        for (int ks = 0; ks < 8; ks++) {
            uint32_t koff = ks * 32;               // 16 halves per k-step
            uint32_t bf[4][4];
            #pragma unroll
            for (int p2 = 0; p2 < 4; p2++)
                ldsm_x4(bf[p2], bB + p2 * (16 * SROWH * 2) + koff);
            uint32_t af[2][4];
            #pragma unroll
            for (int mf = 0; mf < 2; mf++)
                ldsm_x4(af[mf], aBase + mf * (16 * SROWH * 2) + koff);
            #pragma unroll
            for (int mf = 0; mf < 2; mf++)
                #pragma unroll
                for (int nf = 0; nf < 8; nf++)
                    mma_f16(acc[mf][nf], af[mf], &bf[nf >> 1][(nf & 1) * 2]);
        }

        // ---- prefetch next X tile (hides under epilogue) ----
        if (t + 1 < CHUNK && g_tile_ch[idx + 1] >= 0)
            load_x(Xh[(t + 1) & 1], x, g_tile_l0[idx + 1], g_tile_l1[idx + 1], tid);

        // ---- direct epilogue: in-register bias+tanh, residual LDS.16, STG.32 ----
        int l = warp_n ? l1 : l0;
        if (l >= 0) {
            float* ob = out + (size_t)l * C_DIM;
            #pragma unroll
            for (int mf = 0; mf < 2; mf++) {
                int o = wbase + mf * 16 + lr;
                #pragma unroll
                for (int nf = 0; nf < 8; nf++) {
                    int col = n0 + nf * 8 + lc * 2;
                    int b = col & 63;
                    float x00 = __half2float(Xhc[col * SROWH + o]);
                    float x01 = __half2float(Xhc[(col + 1) * SROWH + o]);
                    float x10 = __half2float(Xhc[col * SROWH + o + 8]);
                    float x11 = __half2float(Xhc[(col + 1) * SROWH + o + 8]);
                    float* p0 = ob + (size_t)b * (L_DIM * C_DIM) + o;
                    float* p1 = p0 + (L_DIM * C_DIM);
                    p0[0] = tanh_fast(acc[mf][nf][0] + br[mf][0]) + x00;
                    p1[0] = tanh_fast(acc[mf][nf][1] + br[mf][0]) + x01;
                    p0[8] = tanh_fast(acc[mf][nf][2] + br[mf][1]) + x10;
                    p1[8] = tanh_fast(acc[mf][nf][3] + br[mf][1]) + x11;
                }
            }
        }
    }
}

extern "C" void kernel_launch(void* const* d_in, const int* in_sizes, int n_in,
                              void* d_out, int out_size) {
    const float* x  = (const float*)d_in[0];
    const void*  ch = d_in[1];
    const float* w  = (const float*)d_in[2];
    const float* b  = (const float*)d_in[3];
    float* out = (float*)d_out;

    cudaFuncSetAttribute(dense_kernel, cudaFuncAttributeMaxDynamicSharedMemorySize, SMEM_TOTAL);
    cudaFuncSetAttribute(prep_all, cudaFuncAttributeMaxDynamicSharedMemorySize, L_DIM * 4);

    const long long Y_ELEMS = (long long)B_DIM * L_DIM * C_DIM;   // 67,108,864 fp32
    prep_all<<<1, 1024, L_DIM * 4>>>(ch, out + Y_ELEMS);
    dense_kernel<<<GRID_DENSE, 256, SMEM_TOTAL>>>(x, w, b, out);
}